// round 7
// baseline (speedup 1.0000x reference)
#include <cuda_runtime.h>
#include <cstdint>
#include <cstddef>

// ============================================================================
// Swarm6502 masked 5-expert MoE.
// R7: single fused kernel per 64-token tile:
//   gather-sum h (tf32, smem) -> tf32 MMA vs B (512x256) -> scatter + zero-fill
//   + flag cols (e<2) from smem h. g_H eliminated (~510 MB DRAM saved).
// Pipeline: init -> compact -> precompute_T -> fused.
// ============================================================================

#define NTOK 65536
#define HDIM 512
#define OUTW 1296
#define AMS 516   // Am stride (mod 32 == 4 -> conflict-free a-frag LDS)
#define BSS 264   // Bs stride (mod 32 == 8 -> conflict-free b-frag LDS)

__device__ int   g_counts[5];
__device__ int   g_lists[5][NTOK];
__device__ float g_T[(size_t)5 * 6 * 256 * HDIM];    // 31.5 MB lookup tables

// index source codes: 0=A 1=X 2=Y 3=SP 4=P 5=PCH 6=PCL 7=Op 8=Val 9=carry(P&1)
__constant__ int c_code[5][6] = {
    {0, 8, 9, 7, -1, -1},   // alu
    {0, 8, 9, 7, -1, -1},   // logic
    {0, 1, 2, 8, 7, -1},    // move
    {5, 6, 4, 8, 3, 7},     // flow
    {0, 1, 3, 4, 8, 7}      // stack
};
__constant__ int c_k[5]    = {4, 4, 5, 6, 6};
__constant__ int c_nout[5] = {264, 264, 256, 256, 256};
__constant__ int c_seg[5]  = {0, 264, 528, 784, 1040};

struct PTP  { const float* emb[5]; const float* W1[5]; };
struct FUP  {
    const int*   base[9];
    const float* b1[5];
    const float* B[5];     // Wr (e<2) / Wo (e>=2), 512x256 row-major
    const float* Wf[2];    // 512x8
    float*       out;
};

__device__ __forceinline__ float gelu_tanh(float x) {
    float x3 = x * x * x;
    float t  = tanhf(0.7978845608028654f * (x + 0.044715f * x3));
    return 0.5f * x * (1.0f + t);
}
__device__ __forceinline__ uint32_t f2tf32(float x) {
    uint32_t r;
    asm("cvt.rna.tf32.f32 %0, %1;" : "=r"(r) : "f"(x));
    return r;
}
__device__ __forceinline__ void mma_tf32(float* c, const uint32_t* a,
                                         const uint32_t* b) {
    asm volatile(
        "mma.sync.aligned.m16n8k8.row.col.f32.tf32.tf32.f32 "
        "{%0,%1,%2,%3}, {%4,%5,%6,%7}, {%8,%9}, {%0,%1,%2,%3};"
        : "+f"(c[0]), "+f"(c[1]), "+f"(c[2]), "+f"(c[3])
        : "r"(a[0]), "r"(a[1]), "r"(a[2]), "r"(a[3]), "r"(b[0]), "r"(b[1]));
}

// ---------------- init + compact -----------------------------------------------
__global__ void init_counts() {
    if (threadIdx.x < 5) g_counts[threadIdx.x] = 0;
}
__global__ void compact_kernel(const int* __restrict__ Op,
                               const int* __restrict__ fu_map) {
    int n = blockIdx.x * blockDim.x + threadIdx.x;
    if (n < NTOK) {
        int e   = fu_map[Op[n]];
        int pos = atomicAdd(&g_counts[e], 1);
        g_lists[e][pos] = n;
    }
}

// ---------------- precompute T[e][j] = emb_ej @ W1_ej --------------------------
#define PT_SMEM ((64 * 65 + 64 * 128) * 4)
__global__ void __launch_bounds__(256) precompute_T(PTP p) {
    int z = blockIdx.z, e = z / 6, j = z % 6;
    if (j >= c_k[e]) return;
    int v0 = blockIdx.x * 64;
    int n0 = blockIdx.y * 128;

    extern __shared__ float smp[];
    float (*Es)[65]  = (float(*)[65])smp;
    float (*Ws)[128] = (float(*)[128])(smp + 64 * 65);
    int tid = threadIdx.x;

    {
        int r = tid >> 2, c = (tid & 3) * 16;
        const float* src = p.emb[e] + ((size_t)j * 256 + v0 + r) * 64 + c;
#pragma unroll
        for (int q = 0; q < 16; q++) Es[r][c + q] = __ldg(src + q);
    }
    {
        int r = tid >> 2, c0 = (tid & 3) * 32;
        const float4* src =
            (const float4*)(p.W1[e] + ((size_t)(j * 64 + r)) * HDIM + n0 + c0);
        float4* dst = (float4*)&Ws[r][c0];
#pragma unroll
        for (int q = 0; q < 8; q++) dst[q] = __ldg(src + q);
    }
    __syncthreads();

    float acc[4][8];
#pragma unroll
    for (int i = 0; i < 4; i++)
#pragma unroll
        for (int jj = 0; jj < 8; jj++) acc[i][jj] = 0.f;

    int tm = (tid >> 4) * 4, tn = (tid & 15) * 8;
#pragma unroll
    for (int k = 0; k < 64; k++) {
        float a[4], b[8];
#pragma unroll
        for (int i = 0; i < 4; i++) a[i] = Es[tm + i][k];
        float4 b0 = *(const float4*)&Ws[k][tn];
        float4 b1 = *(const float4*)&Ws[k][tn + 4];
        b[0] = b0.x; b[1] = b0.y; b[2] = b0.z; b[3] = b0.w;
        b[4] = b1.x; b[5] = b1.y; b[6] = b1.z; b[7] = b1.w;
#pragma unroll
        for (int i = 0; i < 4; i++)
#pragma unroll
            for (int jj = 0; jj < 8; jj++)
                acc[i][jj] = fmaf(a[i], b[jj], acc[i][jj]);
    }

    float* T = g_T + ((size_t)(e * 6 + j) * 256) * HDIM;
#pragma unroll
    for (int i = 0; i < 4; i++) {
        float* d = T + (size_t)(v0 + tm + i) * HDIM + n0 + tn;
        *(float4*)d       = make_float4(acc[i][0], acc[i][1], acc[i][2], acc[i][3]);
        *(float4*)(d + 4) = make_float4(acc[i][4], acc[i][5], acc[i][6], acc[i][7]);
    }
}

// ---------------- fused: gather-h -> tf32 MMA -> scatter + flags ----------------
// block = 64 tokens x 256 out-cols. smem: Am[64][516] tf32 h, Bs[64][264].
#define FU_SMEM ((64 * AMS + 64 * BSS) * 4)
__global__ void __launch_bounds__(256) fused_kernel(FUP p) {
    int e  = blockIdx.y;
    int C  = g_counts[e];
    int m0 = blockIdx.x * 64;
    if (m0 >= C) return;

    extern __shared__ uint32_t smf[];
    uint32_t* Am = smf;                  // [64][AMS]
    uint32_t* Bs = smf + 64 * AMS;       // [64][BSS]
    __shared__ int s_tok[64];

    int tid = threadIdx.x;
    if (tid < 64) {
        int m = m0 + tid;
        s_tok[tid] = (m < C) ? g_lists[e][m] : -1;
    }
    __syncthreads();

    int seg = c_seg[e];
    const float* __restrict__ B = p.B[e];

    // ---- zero-fill complement of the 64 token rows (fire-and-forget) ----
    {
        int s4 = seg >> 2;
        int e4 = (seg + c_nout[e]) >> 2;
        float4* out4 = (float4*)p.out;
        float4 z = make_float4(0.f, 0.f, 0.f, 0.f);
        for (int u = tid; u < 64 * (OUTW / 4); u += 256) {
            int m = u / (OUTW / 4);
            int f = u - m * (OUTW / 4);
            if (f >= s4 && f < e4) continue;
            int tok = s_tok[m];
            if (tok < 0) continue;
            out4[(size_t)tok * (OUTW / 4) + f] = z;
        }
    }

    // ---- pre-stage B chunk 0 (latency overlaps the gather below) ----
    {
        int r = tid >> 2, c0 = (tid & 3) * 64;
        const float4* src = (const float4*)(B + (size_t)r * 256 + c0);
        uint32_t* dst = Bs + r * BSS + c0;
#pragma unroll
        for (int q = 0; q < 16; q++) {
            float4 v = __ldg(src + q);
            uint4 u;
            u.x = f2tf32(v.x); u.y = f2tf32(v.y);
            u.z = f2tf32(v.z); u.w = f2tf32(v.w);
            *(uint4*)(dst + q * 4) = u;
        }
    }

    // ---- phase 1: gather-sum h -> Am (tf32, row-major) ----
    {
        int g = tid >> 7, t = tid & 127;     // 2 groups x 128 threads
        int kc = c_k[e];
        float4 bias = __ldg((const float4*)p.b1[e] + t);
        const float* Tb = g_T + ((size_t)(e * 6) << 17);

        for (int lm = g * 32; lm < g * 32 + 32; lm += 2) {
            int tok0 = s_tok[lm], tok1 = s_tok[lm + 1];
            float4 a0 = bias, a1 = bias;
            if ((tok0 | tok1) >= 0 && tok0 >= 0 && tok1 >= 0) {
                for (int j = 0; j < kc; j++) {
                    int code = c_code[e][j];
                    int i0 = (code == 9) ? (__ldg(p.base[4] + tok0) & 1)
                                         : __ldg(p.base[code] + tok0);
                    int i1 = (code == 9) ? (__ldg(p.base[4] + tok1) & 1)
                                         : __ldg(p.base[code] + tok1);
                    const float4* r0 =
                        (const float4*)(Tb + (((size_t)j * 256 + i0) << 9));
                    const float4* r1 =
                        (const float4*)(Tb + (((size_t)j * 256 + i1) << 9));
                    float4 v0 = r0[t], v1 = r1[t];
                    a0.x += v0.x; a0.y += v0.y; a0.z += v0.z; a0.w += v0.w;
                    a1.x += v1.x; a1.y += v1.y; a1.z += v1.z; a1.w += v1.w;
                }
            } else {
                if (tok0 >= 0)
                    for (int j = 0; j < kc; j++) {
                        int code = c_code[e][j];
                        int i0 = (code == 9) ? (__ldg(p.base[4] + tok0) & 1)
                                             : __ldg(p.base[code] + tok0);
                        const float4* r0 =
                            (const float4*)(Tb + (((size_t)j * 256 + i0) << 9));
                        float4 v0 = r0[t];
                        a0.x += v0.x; a0.y += v0.y; a0.z += v0.z; a0.w += v0.w;
                    }
                if (tok1 >= 0)
                    for (int j = 0; j < kc; j++) {
                        int code = c_code[e][j];
                        int i1 = (code == 9) ? (__ldg(p.base[4] + tok1) & 1)
                                             : __ldg(p.base[code] + tok1);
                        const float4* r1 =
                            (const float4*)(Tb + (((size_t)j * 256 + i1) << 9));
                        float4 v1 = r1[t];
                        a1.x += v1.x; a1.y += v1.y; a1.z += v1.z; a1.w += v1.w;
                    }
            }
            uint4 u0 = make_uint4(0, 0, 0, 0), u1 = make_uint4(0, 0, 0, 0);
            if (tok0 >= 0) {
                u0.x = f2tf32(gelu_tanh(a0.x)); u0.y = f2tf32(gelu_tanh(a0.y));
                u0.z = f2tf32(gelu_tanh(a0.z)); u0.w = f2tf32(gelu_tanh(a0.w));
            }
            if (tok1 >= 0) {
                u1.x = f2tf32(gelu_tanh(a1.x)); u1.y = f2tf32(gelu_tanh(a1.y));
                u1.z = f2tf32(gelu_tanh(a1.z)); u1.w = f2tf32(gelu_tanh(a1.w));
            }
            *(uint4*)(Am + lm * AMS + 4 * t)       = u0;
            *(uint4*)(Am + (lm + 1) * AMS + 4 * t) = u1;
        }
    }
    __syncthreads();

    // ---- phase 2: tf32 MMA, 8 K-chunks of 64 ----
    int lane = tid & 31, wrp = tid >> 5;
    int wm = (wrp & 3) * 16;          // 0,16,32,48
    int wn = (wrp >> 2) * 128;        // 0,128
    int grp = lane >> 2, th4 = lane & 3;

    float c[16][4];
#pragma unroll
    for (int nt = 0; nt < 16; nt++)
#pragma unroll
        for (int i = 0; i < 4; i++) c[nt][i] = 0.f;

    int aBase0 = (wm + grp) * AMS + th4;
    int aBase1 = (wm + 8 + grp) * AMS + th4;
    int bBase  = th4 * BSS + wn + grp;

    for (int cc = 0; cc < 8; cc++) {
        int kk = cc * 64;
#pragma unroll
        for (int k8 = 0; k8 < 64; k8 += 8) {
            uint32_t a[4];
            a[0] = Am[aBase0 + kk + k8];
            a[1] = Am[aBase1 + kk + k8];
            a[2] = Am[aBase0 + kk + k8 + 4];
            a[3] = Am[aBase1 + kk + k8 + 4];
#pragma unroll
            for (int nt = 0; nt < 16; nt++) {
                uint32_t b[2];
                b[0] = Bs[bBase + k8 * BSS + nt * 8];
                b[1] = Bs[bBase + (k8 + 4) * BSS + nt * 8];
                mma_tf32(c[nt], a, b);
            }
        }
        __syncthreads();
        if (cc < 7) {
            // stage next B chunk
            int r = tid >> 2, c0 = (tid & 3) * 64;
            const float4* src =
                (const float4*)(B + (size_t)(kk + 64 + r) * 256 + c0);
            uint32_t* dst = Bs + r * BSS + c0;
#pragma unroll
            for (int q = 0; q < 16; q++) {
                float4 v = __ldg(src + q);
                uint4 u;
                u.x = f2tf32(v.x); u.y = f2tf32(v.y);
                u.z = f2tf32(v.z); u.w = f2tf32(v.w);
                *(uint4*)(dst + q * 4) = u;
            }
            __syncthreads();
        }
    }

    // ---- epilogue: scatter MMA results ----
    {
        int r0   = wm + grp;
        int tok0 = s_tok[r0];
        int tok1 = s_tok[r0 + 8];
        if (tok0 >= 0) {
            float* o = p.out + (size_t)tok0 * OUTW + seg + wn + 2 * th4;
#pragma unroll
            for (int nt = 0; nt < 16; nt++)
                *(float2*)(o + nt * 8) = make_float2(c[nt][0], c[nt][1]);
        }
        if (tok1 >= 0) {
            float* o = p.out + (size_t)tok1 * OUTW + seg + wn + 2 * th4;
#pragma unroll
            for (int nt = 0; nt < 16; nt++)
                *(float2*)(o + nt * 8) = make_float2(c[nt][2], c[nt][3]);
        }
    }

    // ---- flags (e<2): out[:,256..263] = h @ Wf, h from smem (tf32) ----
    __syncthreads();
    if (e < 2) {
        // stage Wf (512x8 = 4096 floats) into retired Bs region
        float* sWf = (float*)Bs;
        const float4* Wf4 = (const float4*)p.Wf[e];
        for (int i = tid; i < 1024; i += 256)
            ((float4*)sWf)[i] = __ldg(Wf4 + i);
        __syncthreads();

        const float* AmF = (const float*)Am;
        for (int item = tid; item < 512; item += 256) {
            int m = item >> 3, f = item & 7;
            int tok = s_tok[m];
            if (tok < 0) continue;
            float dot = 0.f;
            const float* hr = AmF + m * AMS;
#pragma unroll 4
            for (int k = 0; k < HDIM; k += 4) {
                float4 hv = *(const float4*)(hr + k);
                dot += hv.x * sWf[(k + 0) * 8 + f];
                dot += hv.y * sWf[(k + 1) * 8 + f];
                dot += hv.z * sWf[(k + 2) * 8 + f];
                dot += hv.w * sWf[(k + 3) * 8 + f];
            }
            p.out[(size_t)tok * OUTW + seg + 256 + f] = dot;
        }
    }
}

// ---------------- host launcher --------------------------------------------------
extern "C" void kernel_launch(void* const* d_in, const int* in_sizes, int n_in,
                              void* d_out, int out_size) {
    (void)in_sizes; (void)n_in; (void)out_size;
    // input order (setup_inputs dict order):
    // 0:A 1:X 2:Y 3:SP 4:P 5:PCH 6:PCL 7:Op 8:Val 9:fu_map
    // 10..24: (emb, W1, b1) x {alu, logic, move, flow, stack}
    // 25:alu_Wr 26:alu_Wf 27:logic_Wr 28:logic_Wf 29:move_Wo 30:flow_Wo 31:stack_Wo
    cudaFuncSetAttribute(precompute_T,
                         cudaFuncAttributeMaxDynamicSharedMemorySize, PT_SMEM);
    cudaFuncSetAttribute(fused_kernel,
                         cudaFuncAttributeMaxDynamicSharedMemorySize, FU_SMEM);

    PTP pt;
    FUP fu;
    for (int i = 0; i < 9; i++) fu.base[i] = (const int*)d_in[i];
    for (int e = 0; e < 5; e++) {
        pt.emb[e] = (const float*)d_in[10 + 3 * e];
        pt.W1[e]  = (const float*)d_in[11 + 3 * e];
        fu.b1[e]  = (const float*)d_in[12 + 3 * e];
    }
    fu.B[0]  = (const float*)d_in[25];   // alu_Wr
    fu.B[1]  = (const float*)d_in[27];   // logic_Wr
    fu.B[2]  = (const float*)d_in[29];   // move_Wo
    fu.B[3]  = (const float*)d_in[30];   // flow_Wo
    fu.B[4]  = (const float*)d_in[31];   // stack_Wo
    fu.Wf[0] = (const float*)d_in[26];   // alu_Wf
    fu.Wf[1] = (const float*)d_in[28];   // logic_Wf
    fu.out   = (float*)d_out;

    const int* Op = (const int*)d_in[7];
    const int* fump = (const int*)d_in[9];

    init_counts<<<1, 32>>>();
    compact_kernel<<<NTOK / 256, 256>>>(Op, fump);
    precompute_T<<<dim3(4, 4, 30), 256, PT_SMEM>>>(pt);
    fused_kernel<<<dim3(1024, 5), 256, FU_SMEM>>>(fu);
}

// round 8
// speedup vs baseline: 1.2261x; 1.2261x over previous
#include <cuda_runtime.h>
#include <cstdint>
#include <cstddef>

// ============================================================================
// Swarm6502 masked 5-expert MoE. R8 = R6 pipeline with:
//  - gemm2: A direct-from-global (no A smem), double-buffered B, 1 barrier/chunk
//  - h_kernel: 4-token ILP fast path
// Pipeline: init -> compact -> precompute_T -> h -> flag -> gemm2(+zero-fill)
// ============================================================================

#define NTOK 65536
#define HDIM 512
#define OUTW 1296

__device__ int   g_counts[5];
__device__ int   g_lists[5][NTOK];
__device__ float g_H[(size_t)NTOK * HDIM];           // 134 MB hidden
__device__ float g_T[(size_t)5 * 6 * 256 * HDIM];    // 31.5 MB lookup tables

// index source codes: 0=A 1=X 2=Y 3=SP 4=P 5=PCH 6=PCL 7=Op 8=Val 9=carry(P&1)
__constant__ int c_code[5][6] = {
    {0, 8, 9, 7, -1, -1},   // alu
    {0, 8, 9, 7, -1, -1},   // logic
    {0, 1, 2, 8, 7, -1},    // move
    {5, 6, 4, 8, 3, 7},     // flow
    {0, 1, 3, 4, 8, 7}      // stack
};
__constant__ int c_k[5]    = {4, 4, 5, 6, 6};
__constant__ int c_nout[5] = {264, 264, 256, 256, 256};
__constant__ int c_seg[5]  = {0, 264, 528, 784, 1040};

struct PTP { const float* emb[5]; const float* W1[5]; };
struct HP  { const int* base[9]; const float* b1[5]; };
struct FP  { const float* Wf[2]; float* out; };
struct G2P { const float* B[5]; float* out; };

__device__ __forceinline__ float gelu_tanh(float x) {
    float x3 = x * x * x;
    float t  = tanhf(0.7978845608028654f * (x + 0.044715f * x3));
    return 0.5f * x * (1.0f + t);
}
__device__ __forceinline__ uint32_t f2tf32(float x) {
    uint32_t r;
    asm("cvt.rna.tf32.f32 %0, %1;" : "=r"(r) : "f"(x));
    return r;
}
__device__ __forceinline__ void mma_tf32(float* c, const uint32_t* a,
                                         const uint32_t* b) {
    asm volatile(
        "mma.sync.aligned.m16n8k8.row.col.f32.tf32.tf32.f32 "
        "{%0,%1,%2,%3}, {%4,%5,%6,%7}, {%8,%9}, {%0,%1,%2,%3};"
        : "+f"(c[0]), "+f"(c[1]), "+f"(c[2]), "+f"(c[3])
        : "r"(a[0]), "r"(a[1]), "r"(a[2]), "r"(a[3]), "r"(b[0]), "r"(b[1]));
}

// ---------------- init + compact -----------------------------------------------
__global__ void init_counts() {
    if (threadIdx.x < 5) g_counts[threadIdx.x] = 0;
}
__global__ void compact_kernel(const int* __restrict__ Op,
                               const int* __restrict__ fu_map) {
    int n = blockIdx.x * blockDim.x + threadIdx.x;
    if (n < NTOK) {
        int e   = fu_map[Op[n]];
        int pos = atomicAdd(&g_counts[e], 1);
        g_lists[e][pos] = n;
    }
}

// ---------------- precompute T[e][j] = emb_ej @ W1_ej --------------------------
#define PT_SMEM ((64 * 65 + 64 * 128) * 4)
__global__ void __launch_bounds__(256) precompute_T(PTP p) {
    int z = blockIdx.z, e = z / 6, j = z % 6;
    if (j >= c_k[e]) return;
    int v0 = blockIdx.x * 64;
    int n0 = blockIdx.y * 128;

    extern __shared__ float smp[];
    float (*Es)[65]  = (float(*)[65])smp;
    float (*Ws)[128] = (float(*)[128])(smp + 64 * 65);
    int tid = threadIdx.x;

    {
        int r = tid >> 2, c = (tid & 3) * 16;
        const float* src = p.emb[e] + ((size_t)j * 256 + v0 + r) * 64 + c;
#pragma unroll
        for (int q = 0; q < 16; q++) Es[r][c + q] = __ldg(src + q);
    }
    {
        int r = tid >> 2, c0 = (tid & 3) * 32;
        const float4* src =
            (const float4*)(p.W1[e] + ((size_t)(j * 64 + r)) * HDIM + n0 + c0);
        float4* dst = (float4*)&Ws[r][c0];
#pragma unroll
        for (int q = 0; q < 8; q++) dst[q] = __ldg(src + q);
    }
    __syncthreads();

    float acc[4][8];
#pragma unroll
    for (int i = 0; i < 4; i++)
#pragma unroll
        for (int jj = 0; jj < 8; jj++) acc[i][jj] = 0.f;

    int tm = (tid >> 4) * 4, tn = (tid & 15) * 8;
#pragma unroll
    for (int k = 0; k < 64; k++) {
        float a[4], b[8];
#pragma unroll
        for (int i = 0; i < 4; i++) a[i] = Es[tm + i][k];
        float4 b0 = *(const float4*)&Ws[k][tn];
        float4 b1 = *(const float4*)&Ws[k][tn + 4];
        b[0] = b0.x; b[1] = b0.y; b[2] = b0.z; b[3] = b0.w;
        b[4] = b1.x; b[5] = b1.y; b[6] = b1.z; b[7] = b1.w;
#pragma unroll
        for (int i = 0; i < 4; i++)
#pragma unroll
            for (int jj = 0; jj < 8; jj++)
                acc[i][jj] = fmaf(a[i], b[jj], acc[i][jj]);
    }

    float* T = g_T + ((size_t)(e * 6 + j) * 256) * HDIM;
#pragma unroll
    for (int i = 0; i < 4; i++) {
        float* d = T + (size_t)(v0 + tm + i) * HDIM + n0 + tn;
        *(float4*)d       = make_float4(acc[i][0], acc[i][1], acc[i][2], acc[i][3]);
        *(float4*)(d + 4) = make_float4(acc[i][4], acc[i][5], acc[i][6], acc[i][7]);
    }
}

// ---------------- h = gelu(sum_j T[e][j][idx_j] + b1), 4-token ILP --------------
__global__ void __launch_bounds__(256) h_kernel(HP p) {
    int e  = blockIdx.y;
    int C  = g_counts[e];
    int m0 = blockIdx.x * 64;
    if (m0 >= C) return;

    int tid = threadIdx.x;
    int g   = tid >> 7, t = tid & 127;
    int kc  = c_k[e];
    float4 bias = __ldg((const float4*)p.b1[e] + t);
    const float* Tb = g_T + ((size_t)(e * 6) << 17);

    if (m0 + 64 <= C) {
        const int* lst = g_lists[e] + m0 + g;
        for (int s = 0; s < 32; s += 4) {
            int tk[4];
#pragma unroll
            for (int u = 0; u < 4; u++) tk[u] = lst[(s + u) * 2];
            float4 ac[4];
#pragma unroll
            for (int u = 0; u < 4; u++) ac[u] = bias;
            for (int j = 0; j < kc; j++) {
                int code = c_code[e][j];
                int id[4];
#pragma unroll
                for (int u = 0; u < 4; u++)
                    id[u] = (code == 9) ? (__ldg(p.base[4] + tk[u]) & 1)
                                        : __ldg(p.base[code] + tk[u]);
#pragma unroll
                for (int u = 0; u < 4; u++) {
                    float4 v = ((const float4*)(
                        Tb + (((size_t)j * 256 + id[u]) << 9)))[t];
                    ac[u].x += v.x; ac[u].y += v.y;
                    ac[u].z += v.z; ac[u].w += v.w;
                }
            }
#pragma unroll
            for (int u = 0; u < 4; u++) {
                float4 r;
                r.x = gelu_tanh(ac[u].x); r.y = gelu_tanh(ac[u].y);
                r.z = gelu_tanh(ac[u].z); r.w = gelu_tanh(ac[u].w);
                ((float4*)(g_H + ((size_t)tk[u] << 9)))[t] = r;
            }
        }
    } else {
        int mEnd = C;
        for (int mi = m0 + g; mi < mEnd; mi += 2) {
            int tok = g_lists[e][mi];
            float4 acc = bias;
            for (int j = 0; j < kc; j++) {
                int code = c_code[e][j];
                int idx  = (code == 9) ? (__ldg(p.base[4] + tok) & 1)
                                       : __ldg(p.base[code] + tok);
                const float4* row =
                    (const float4*)(Tb + (((size_t)j * 256 + idx) << 9));
                float4 v = row[t];
                acc.x += v.x; acc.y += v.y; acc.z += v.z; acc.w += v.w;
            }
            float4 r;
            r.x = gelu_tanh(acc.x); r.y = gelu_tanh(acc.y);
            r.z = gelu_tanh(acc.z); r.w = gelu_tanh(acc.w);
            ((float4*)(g_H + ((size_t)tok << 9)))[t] = r;
        }
    }
}

// ---------------- flag cols (alu/logic) -----------------------------------------
__global__ void __launch_bounds__(256) flag_kernel(FP p) {
    int e  = blockIdx.y;
    int C  = g_counts[e];
    int m0 = blockIdx.x * 32;
    if (m0 >= C) return;

    __shared__ float sWf[HDIM][8];
    int tid = threadIdx.x;
    const float4* Wf4 = (const float4*)p.Wf[e];
#pragma unroll
    for (int i = 0; i < 4; i++)
        ((float4*)sWf)[tid + i * 256] = __ldg(Wf4 + tid + i * 256);
    __syncthreads();

    int r = tid >> 3, f = tid & 7;
    int mi = m0 + r;
    if (mi >= C) return;
    int tok = g_lists[e][mi];
    const float4* h = (const float4*)(g_H + ((size_t)tok << 9));
    float dot = 0.f;
#pragma unroll 4
    for (int k4 = 0; k4 < 128; k4++) {
        float4 hv = __ldg(h + k4);
        dot += hv.x * sWf[k4 * 4 + 0][f];
        dot += hv.y * sWf[k4 * 4 + 1][f];
        dot += hv.z * sWf[k4 * 4 + 2][f];
        dot += hv.w * sWf[k4 * 4 + 3][f];
    }
    p.out[(size_t)tok * OUTW + c_seg[e] + 256 + f] = dot;
}

// ---------------- gemm2: tf32 MMA, A from global, double-buffered B --------------
// (C x 512) @ (512 x 256). BM=128, BN=128, BK=32. 8 warps; warp tile 32x64.
__global__ void __launch_bounds__(256, 2) gemm2_kernel(G2P p) {
    int e  = blockIdx.z;
    int C  = g_counts[e];
    int m0 = blockIdx.x * 128;
    if (m0 >= C) return;
    int n0 = blockIdx.y * 128;

    __shared__ uint32_t Bs[2][32][136];   // stride 136: conflict-free b-frag LDS
    __shared__ int s_tok[128];

    int tid = threadIdx.x;
    if (tid < 128) {
        int m = m0 + tid;
        s_tok[tid] = (m < C) ? g_lists[e][m] : -1;
    }
    __syncthreads();

    // zero-fill complement of the 1296-wide rows (y==0 blocks only)
    if (blockIdx.y == 0) {
        int s4 = c_seg[e] >> 2;
        int e4 = (c_seg[e] + c_nout[e]) >> 2;
        float4* out4 = (float4*)p.out;
        float4 z = make_float4(0.f, 0.f, 0.f, 0.f);
        for (int u = tid; u < 128 * (OUTW / 4); u += 256) {
            int m = u / (OUTW / 4);
            int f = u - m * (OUTW / 4);
            if (f >= s4 && f < e4) continue;
            int tok = s_tok[m];
            if (tok < 0) continue;
            out4[(size_t)tok * (OUTW / 4) + f] = z;
        }
    }

    int lane = tid & 31, wrp = tid >> 5;
    int wm = (wrp & 3) * 32;        // warp row base
    int wn = (wrp >> 2) * 64;       // warp col base
    int grp = lane >> 2, th4 = lane & 3;

    // 4 fixed g_H rows per lane: i=0,1 -> mt0 (rows wm+grp, wm+8+grp);
    //                            i=2,3 -> mt1 (rows wm+16+grp, wm+24+grp)
    const float* ap[4];
    bool am[4];
#pragma unroll
    for (int i = 0; i < 4; i++) {
        int tok = s_tok[wm + i * 8 + grp];
        am[i]   = (tok >= 0);
        ap[i]   = g_H + ((size_t)(tok >= 0 ? tok : 0) << 9);
    }

    float c[2][8][4];
#pragma unroll
    for (int mt = 0; mt < 2; mt++)
#pragma unroll
        for (int nt = 0; nt < 8; nt++)
#pragma unroll
            for (int i = 0; i < 4; i++) c[mt][nt][i] = 0.f;

    const float* __restrict__ Bg = p.B[e];
    int sb_k = tid >> 3, sb_n = (tid & 7) * 16;

    // stage B chunk 0
    {
        const float4* src = (const float4*)(Bg + (size_t)sb_k * 256 + n0 + sb_n);
#pragma unroll
        for (int q = 0; q < 4; q++) {
            float4 v = __ldg(src + q);
            uint4 u;
            u.x = f2tf32(v.x); u.y = f2tf32(v.y);
            u.z = f2tf32(v.z); u.w = f2tf32(v.w);
            *(uint4*)&Bs[0][sb_k][sb_n + q * 4] = u;
        }
    }
    __syncthreads();

    float4 pf[4];
    for (int cc = 0; cc < 16; cc++) {
        int cur = cc & 1;
        if (cc < 15) {
            const float4* src =
                (const float4*)(Bg + (size_t)(cc * 32 + 32 + sb_k) * 256 + n0 + sb_n);
#pragma unroll
            for (int q = 0; q < 4; q++) pf[q] = __ldg(src + q);
            // L2-prefetch next chunk's A lines
#pragma unroll
            for (int i = 0; i < 4; i++) {
                const float* pa = ap[i] + (cc + 1) * 32 + th4;
                asm volatile("prefetch.global.L2 [%0];" ::"l"(pa));
            }
        }
#pragma unroll
        for (int k8 = 0; k8 < 32; k8 += 8) {
            int k = cc * 32 + k8 + th4;
            uint32_t a0[4], a1[4];
            float v;
            v = am[0] ? __ldg(ap[0] + k)     : 0.f; a0[0] = f2tf32(v);
            v = am[1] ? __ldg(ap[1] + k)     : 0.f; a0[1] = f2tf32(v);
            v = am[0] ? __ldg(ap[0] + k + 4) : 0.f; a0[2] = f2tf32(v);
            v = am[1] ? __ldg(ap[1] + k + 4) : 0.f; a0[3] = f2tf32(v);
            v = am[2] ? __ldg(ap[2] + k)     : 0.f; a1[0] = f2tf32(v);
            v = am[3] ? __ldg(ap[3] + k)     : 0.f; a1[1] = f2tf32(v);
            v = am[2] ? __ldg(ap[2] + k + 4) : 0.f; a1[2] = f2tf32(v);
            v = am[3] ? __ldg(ap[3] + k + 4) : 0.f; a1[3] = f2tf32(v);
#pragma unroll
            for (int nt = 0; nt < 8; nt++) {
                uint32_t b[2];
                b[0] = Bs[cur][k8 + th4][wn + nt * 8 + grp];
                b[1] = Bs[cur][k8 + th4 + 4][wn + nt * 8 + grp];
                mma_tf32(c[0][nt], a0, b);
                mma_tf32(c[1][nt], a1, b);
            }
        }
        if (cc < 15) {
#pragma unroll
            for (int q = 0; q < 4; q++) {
                uint4 u;
                u.x = f2tf32(pf[q].x); u.y = f2tf32(pf[q].y);
                u.z = f2tf32(pf[q].z); u.w = f2tf32(pf[q].w);
                *(uint4*)&Bs[cur ^ 1][sb_k][sb_n + q * 4] = u;
            }
        }
        __syncthreads();
    }

    // epilogue
    int seg = c_seg[e];
#pragma unroll
    for (int mt = 0; mt < 2; mt++) {
        int r0   = wm + mt * 16 + grp;
        int tok0 = s_tok[r0];
        int tok1 = s_tok[r0 + 8];
        if (tok0 >= 0) {
            float* o = p.out + (size_t)tok0 * OUTW + seg + n0 + wn + 2 * th4;
#pragma unroll
            for (int nt = 0; nt < 8; nt++)
                *(float2*)(o + nt * 8) = make_float2(c[mt][nt][0], c[mt][nt][1]);
        }
        if (tok1 >= 0) {
            float* o = p.out + (size_t)tok1 * OUTW + seg + n0 + wn + 2 * th4;
#pragma unroll
            for (int nt = 0; nt < 8; nt++)
                *(float2*)(o + nt * 8) = make_float2(c[mt][nt][2], c[mt][nt][3]);
        }
    }
}

// ---------------- host launcher ---------------------------------------------------
extern "C" void kernel_launch(void* const* d_in, const int* in_sizes, int n_in,
                              void* d_out, int out_size) {
    (void)in_sizes; (void)n_in; (void)out_size;
    // input order (setup_inputs dict order):
    // 0:A 1:X 2:Y 3:SP 4:P 5:PCH 6:PCL 7:Op 8:Val 9:fu_map
    // 10..24: (emb, W1, b1) x {alu, logic, move, flow, stack}
    // 25:alu_Wr 26:alu_Wf 27:logic_Wr 28:logic_Wf 29:move_Wo 30:flow_Wo 31:stack_Wo
    cudaFuncSetAttribute(precompute_T,
                         cudaFuncAttributeMaxDynamicSharedMemorySize, PT_SMEM);

    PTP pt;
    HP  hp;
    for (int i = 0; i < 9; i++) hp.base[i] = (const int*)d_in[i];
    for (int e = 0; e < 5; e++) {
        pt.emb[e] = (const float*)d_in[10 + 3 * e];
        pt.W1[e]  = (const float*)d_in[11 + 3 * e];
        hp.b1[e]  = (const float*)d_in[12 + 3 * e];
    }
    FP fp;
    fp.Wf[0] = (const float*)d_in[26];
    fp.Wf[1] = (const float*)d_in[28];
    fp.out   = (float*)d_out;

    G2P p2;
    p2.out  = (float*)d_out;
    p2.B[0] = (const float*)d_in[25];
    p2.B[1] = (const float*)d_in[27];
    p2.B[2] = (const float*)d_in[29];
    p2.B[3] = (const float*)d_in[30];
    p2.B[4] = (const float*)d_in[31];

    const int* Op = (const int*)d_in[7];
    const int* fu = (const int*)d_in[9];

    init_counts<<<1, 32>>>();
    compact_kernel<<<NTOK / 256, 256>>>(Op, fu);
    precompute_T<<<dim3(4, 4, 30), 256, PT_SMEM>>>(pt);
    h_kernel<<<dim3(1024, 5), 256>>>(hp);
    flag_kernel<<<dim3(2048, 2), 256>>>(fp);
    gemm2_kernel<<<dim3(512, 2, 5), 256>>>(p2);
}

// round 10
// speedup vs baseline: 1.3159x; 1.0733x over previous
#include <cuda_runtime.h>
#include <cstdint>
#include <cstddef>

// ============================================================================
// Swarm6502 masked 5-expert MoE. R10 = R9 with gemm2 tiles in DYNAMIC smem
// (70 KB > 48 KB static limit; opt-in via cudaFuncSetAttribute).
// Pipeline: compact -> precompute_T -> h -> gemm2(+zero-fill) -> flag -> reset
// ============================================================================

#define NTOK 65536
#define HDIM 512
#define OUTW 1296
#define SST 136   // smem tile stride: bank=(8k+x)%32 bijective per warp

__device__ int   g_counts[5];                        // zero-init at load
__device__ int   g_lists[5][NTOK];
__device__ float g_H[(size_t)NTOK * HDIM];           // 134 MB hidden
__device__ float g_T[(size_t)5 * 6 * 256 * HDIM];    // 31.5 MB lookup tables

// index source codes: 0=A 1=X 2=Y 3=SP 4=P 5=PCH 6=PCL 7=Op 8=Val 9=carry(P&1)
__constant__ int c_code[5][6] = {
    {0, 8, 9, 7, -1, -1},   // alu
    {0, 8, 9, 7, -1, -1},   // logic
    {0, 1, 2, 8, 7, -1},    // move
    {5, 6, 4, 8, 3, 7},     // flow
    {0, 1, 3, 4, 8, 7}      // stack
};
__constant__ int c_k[5]    = {4, 4, 5, 6, 6};
__constant__ int c_nout[5] = {264, 264, 256, 256, 256};
__constant__ int c_seg[5]  = {0, 264, 528, 784, 1040};

struct PTP { const float* emb[5]; const float* W1[5]; };
struct HP  { const int* base[9]; const float* b1[5]; };
struct FP  { const float* Wf[2]; float* out; };
struct G2P { const float* B[5]; float* out; };

__device__ __forceinline__ float gelu_tanh(float x) {
    float x3 = x * x * x;
    float t  = tanhf(0.7978845608028654f * (x + 0.044715f * x3));
    return 0.5f * x * (1.0f + t);
}
__device__ __forceinline__ uint32_t f2tf32(float x) {
    uint32_t r;
    asm("cvt.rna.tf32.f32 %0, %1;" : "=r"(r) : "f"(x));
    return r;
}
__device__ __forceinline__ void mma_tf32(float* c, const uint32_t* a,
                                         const uint32_t* b) {
    asm volatile(
        "mma.sync.aligned.m16n8k8.row.col.f32.tf32.tf32.f32 "
        "{%0,%1,%2,%3}, {%4,%5,%6,%7}, {%8,%9}, {%0,%1,%2,%3};"
        : "+f"(c[0]), "+f"(c[1]), "+f"(c[2]), "+f"(c[3])
        : "r"(a[0]), "r"(a[1]), "r"(a[2]), "r"(a[3]), "r"(b[0]), "r"(b[1]));
}

// ---------------- compact (counts zero on entry; reset kernel restores) --------
__global__ void compact_kernel(const int* __restrict__ Op,
                               const int* __restrict__ fu_map) {
    int n = blockIdx.x * blockDim.x + threadIdx.x;
    if (n < NTOK) {
        int e   = fu_map[Op[n]];
        int pos = atomicAdd(&g_counts[e], 1);
        g_lists[e][pos] = n;
    }
}
__global__ void reset_counts() {
    if (threadIdx.x < 5) g_counts[threadIdx.x] = 0;
}

// ---------------- precompute T[e][j] = emb_ej @ W1_ej --------------------------
#define PT_SMEM ((64 * 65 + 64 * 128) * 4)
__global__ void __launch_bounds__(256) precompute_T(PTP p) {
    int z = blockIdx.z, e = z / 6, j = z % 6;
    if (j >= c_k[e]) return;
    int v0 = blockIdx.x * 64;
    int n0 = blockIdx.y * 128;

    extern __shared__ float smp[];
    float (*Es)[65]  = (float(*)[65])smp;
    float (*Ws)[128] = (float(*)[128])(smp + 64 * 65);
    int tid = threadIdx.x;

    {
        int r = tid >> 2, c = (tid & 3) * 16;
        const float* src = p.emb[e] + ((size_t)j * 256 + v0 + r) * 64 + c;
#pragma unroll
        for (int q = 0; q < 16; q++) Es[r][c + q] = __ldg(src + q);
    }
    {
        int r = tid >> 2, c0 = (tid & 3) * 32;
        const float4* src =
            (const float4*)(p.W1[e] + ((size_t)(j * 64 + r)) * HDIM + n0 + c0);
        float4* dst = (float4*)&Ws[r][c0];
#pragma unroll
        for (int q = 0; q < 8; q++) dst[q] = __ldg(src + q);
    }
    __syncthreads();

    float acc[4][8];
#pragma unroll
    for (int i = 0; i < 4; i++)
#pragma unroll
        for (int jj = 0; jj < 8; jj++) acc[i][jj] = 0.f;

    int tm = (tid >> 4) * 4, tn = (tid & 15) * 8;
#pragma unroll
    for (int k = 0; k < 64; k++) {
        float a[4], b[8];
#pragma unroll
        for (int i = 0; i < 4; i++) a[i] = Es[tm + i][k];
        float4 b0 = *(const float4*)&Ws[k][tn];
        float4 b1 = *(const float4*)&Ws[k][tn + 4];
        b[0] = b0.x; b[1] = b0.y; b[2] = b0.z; b[3] = b0.w;
        b[4] = b1.x; b[5] = b1.y; b[6] = b1.z; b[7] = b1.w;
#pragma unroll
        for (int i = 0; i < 4; i++)
#pragma unroll
            for (int jj = 0; jj < 8; jj++)
                acc[i][jj] = fmaf(a[i], b[jj], acc[i][jj]);
    }

    float* T = g_T + ((size_t)(e * 6 + j) * 256) * HDIM;
#pragma unroll
    for (int i = 0; i < 4; i++) {
        float* d = T + (size_t)(v0 + tm + i) * HDIM + n0 + tn;
        *(float4*)d       = make_float4(acc[i][0], acc[i][1], acc[i][2], acc[i][3]);
        *(float4*)(d + 4) = make_float4(acc[i][4], acc[i][5], acc[i][6], acc[i][7]);
    }
}

// ---------------- h = gelu(sum_j T[e][j][idx_j] + b1) ---------------------------
__global__ void __launch_bounds__(256) h_kernel(HP p) {
    int e  = blockIdx.y;
    int C  = g_counts[e];
    int m0 = blockIdx.x * 64;
    if (m0 >= C) return;

    int tid = threadIdx.x;
    int g   = tid >> 7, t = tid & 127;
    int kc  = c_k[e];
    float4 bias = __ldg((const float4*)p.b1[e] + t);
    const float* Tb = g_T + ((size_t)(e * 6) << 17);

    int mEnd = m0 + 64;
    if (mEnd > C) mEnd = C;
    int mi = m0 + g;
    for (; mi + 2 < mEnd; mi += 4) {
        int tok0 = g_lists[e][mi];
        int tok1 = g_lists[e][mi + 2];
        float4 a0 = bias, a1 = bias;
        for (int j = 0; j < kc; j++) {
            int code = c_code[e][j];
            int i0 = (code == 9) ? (__ldg(p.base[4] + tok0) & 1)
                                 : __ldg(p.base[code] + tok0);
            int i1 = (code == 9) ? (__ldg(p.base[4] + tok1) & 1)
                                 : __ldg(p.base[code] + tok1);
            float4 v0 = ((const float4*)(Tb + (((size_t)j * 256 + i0) << 9)))[t];
            float4 v1 = ((const float4*)(Tb + (((size_t)j * 256 + i1) << 9)))[t];
            a0.x += v0.x; a0.y += v0.y; a0.z += v0.z; a0.w += v0.w;
            a1.x += v1.x; a1.y += v1.y; a1.z += v1.z; a1.w += v1.w;
        }
        float4 o0, o1;
        o0.x = gelu_tanh(a0.x); o0.y = gelu_tanh(a0.y);
        o0.z = gelu_tanh(a0.z); o0.w = gelu_tanh(a0.w);
        o1.x = gelu_tanh(a1.x); o1.y = gelu_tanh(a1.y);
        o1.z = gelu_tanh(a1.z); o1.w = gelu_tanh(a1.w);
        ((float4*)(g_H + ((size_t)tok0 << 9)))[t] = o0;
        ((float4*)(g_H + ((size_t)tok1 << 9)))[t] = o1;
    }
    for (; mi < mEnd; mi += 2) {
        int tok = g_lists[e][mi];
        float4 acc = bias;
        for (int j = 0; j < kc; j++) {
            int code = c_code[e][j];
            int idx  = (code == 9) ? (__ldg(p.base[4] + tok) & 1)
                                   : __ldg(p.base[code] + tok);
            float4 v = ((const float4*)(Tb + (((size_t)j * 256 + idx) << 9)))[t];
            acc.x += v.x; acc.y += v.y; acc.z += v.z; acc.w += v.w;
        }
        float4 r;
        r.x = gelu_tanh(acc.x); r.y = gelu_tanh(acc.y);
        r.z = gelu_tanh(acc.z); r.w = gelu_tanh(acc.w);
        ((float4*)(g_H + ((size_t)tok << 9)))[t] = r;
    }
}

// ---------------- flag cols (alu/logic) -----------------------------------------
__global__ void __launch_bounds__(256) flag_kernel(FP p) {
    int e  = blockIdx.y;
    int C  = g_counts[e];
    int m0 = blockIdx.x * 32;
    if (m0 >= C) return;

    __shared__ float sWf[HDIM][8];
    int tid = threadIdx.x;
    const float4* Wf4 = (const float4*)p.Wf[e];
#pragma unroll
    for (int i = 0; i < 4; i++)
        ((float4*)sWf)[tid + i * 256] = __ldg(Wf4 + tid + i * 256);
    __syncthreads();

    int r = tid >> 3, f = tid & 7;
    int mi = m0 + r;
    if (mi >= C) return;
    int tok = g_lists[e][mi];
    const float4* h = (const float4*)(g_H + ((size_t)tok << 9));
    float dot = 0.f;
#pragma unroll 4
    for (int k4 = 0; k4 < 128; k4++) {
        float4 hv = __ldg(h + k4);
        dot += hv.x * sWf[k4 * 4 + 0][f];
        dot += hv.y * sWf[k4 * 4 + 1][f];
        dot += hv.z * sWf[k4 * 4 + 2][f];
        dot += hv.w * sWf[k4 * 4 + 3][f];
    }
    p.out[(size_t)tok * OUTW + c_seg[e] + 256 + f] = dot;
}

// ---------------- gemm2 v3: tf32 MMA, double-buffered A+B (dynamic smem) --------
// (C x 512) @ (512 x 256). BM=128, BN=128, BK=32. 8 warps; warp tile 32x64.
// dynamic smem: 2 bufs x (As 32xSST + Bs 32xSST) x 4 B = 69632 B
#define G2_SMEM (2 * 2 * 32 * SST * 4)
__global__ void __launch_bounds__(256) gemm2_kernel(G2P p) {
    int e  = blockIdx.z;
    int C  = g_counts[e];
    int m0 = blockIdx.x * 128;
    if (m0 >= C) return;
    int n0 = blockIdx.y * 128;

    extern __shared__ uint32_t smg[];
    // layout: As[2][32][SST], Bs[2][32][SST]
    uint32_t (*As)[32][SST] = (uint32_t(*)[32][SST])smg;
    uint32_t (*Bs)[32][SST] = (uint32_t(*)[32][SST])(smg + 2 * 32 * SST);
    __shared__ int s_tok[128];

    int tid = threadIdx.x;
    if (tid < 128) {
        int m = m0 + tid;
        s_tok[tid] = (m < C) ? g_lists[e][m] : -1;
    }
    __syncthreads();

    // zero-fill complement of the 1296-wide rows (y==0 blocks only)
    if (blockIdx.y == 0) {
        int s4 = c_seg[e] >> 2;
        int e4 = (c_seg[e] + c_nout[e]) >> 2;
        float4* out4 = (float4*)p.out;
        float4 z = make_float4(0.f, 0.f, 0.f, 0.f);
        for (int u = tid; u < 128 * (OUTW / 4); u += 256) {
            int m = u / (OUTW / 4);
            int f = u - m * (OUTW / 4);
            if (f >= s4 && f < e4) continue;
            int tok = s_tok[m];
            if (tok < 0) continue;
            out4[(size_t)tok * (OUTW / 4) + f] = z;
        }
    }

    int lane = tid & 31, wrp = tid >> 5;
    int wm = (wrp & 3) * 32;
    int wn = (wrp >> 2) * 64;
    int grp = lane >> 2, th4 = lane & 3;

    float c[2][8][4];
#pragma unroll
    for (int mt = 0; mt < 2; mt++)
#pragma unroll
        for (int nt = 0; nt < 8; nt++)
#pragma unroll
            for (int i = 0; i < 4; i++) c[mt][nt][i] = 0.f;

    // staging assignments
    int sa_m   = tid & 127;
    int sa_kq  = (tid >> 7) * 16;
    int sa_tok = s_tok[sa_m];
    const float4* arow =
        (const float4*)(g_H + ((size_t)(sa_tok >= 0 ? sa_tok : 0) << 9));
    int sb_k = tid >> 3, sb_n = (tid & 7) * 16;
    const float* __restrict__ Bg = p.B[e];

    float4 pa[4], pb[4];
    // load chunk 0 into regs
#pragma unroll
    for (int q = 0; q < 4; q++)
        pa[q] = (sa_tok >= 0) ? __ldg(arow + (sa_kq >> 2) + q)
                              : make_float4(0.f, 0.f, 0.f, 0.f);
    {
        const float4* src = (const float4*)(Bg + (size_t)sb_k * 256 + n0 + sb_n);
#pragma unroll
        for (int q = 0; q < 4; q++) pb[q] = __ldg(src + q);
    }
    // STS chunk 0 -> buffer 0
#pragma unroll
    for (int q = 0; q < 4; q++) {
        As[0][sa_kq + q * 4 + 0][sa_m] = f2tf32(pa[q].x);
        As[0][sa_kq + q * 4 + 1][sa_m] = f2tf32(pa[q].y);
        As[0][sa_kq + q * 4 + 2][sa_m] = f2tf32(pa[q].z);
        As[0][sa_kq + q * 4 + 3][sa_m] = f2tf32(pa[q].w);
        uint4 u;
        u.x = f2tf32(pb[q].x); u.y = f2tf32(pb[q].y);
        u.z = f2tf32(pb[q].z); u.w = f2tf32(pb[q].w);
        *(uint4*)&Bs[0][sb_k][sb_n + q * 4] = u;
    }
    __syncthreads();

    for (int cc = 0; cc < 16; cc++) {
        int cur = cc & 1;
        if (cc < 15) {
            int kk = cc * 32 + 32;
#pragma unroll
            for (int q = 0; q < 4; q++)
                pa[q] = (sa_tok >= 0) ? __ldg(arow + ((kk + sa_kq) >> 2) + q)
                                      : make_float4(0.f, 0.f, 0.f, 0.f);
            const float4* src =
                (const float4*)(Bg + (size_t)(kk + sb_k) * 256 + n0 + sb_n);
#pragma unroll
            for (int q = 0; q < 4; q++) pb[q] = __ldg(src + q);
        }

#pragma unroll
        for (int k8 = 0; k8 < 32; k8 += 8) {
            uint32_t a[2][4], b[8][2];
#pragma unroll
            for (int mt = 0; mt < 2; mt++) {
                int mb = wm + mt * 16;
                a[mt][0] = As[cur][k8 + th4][mb + grp];
                a[mt][1] = As[cur][k8 + th4][mb + 8 + grp];
                a[mt][2] = As[cur][k8 + th4 + 4][mb + grp];
                a[mt][3] = As[cur][k8 + th4 + 4][mb + 8 + grp];
            }
#pragma unroll
            for (int nt = 0; nt < 8; nt++) {
                b[nt][0] = Bs[cur][k8 + th4][wn + nt * 8 + grp];
                b[nt][1] = Bs[cur][k8 + th4 + 4][wn + nt * 8 + grp];
            }
#pragma unroll
            for (int mt = 0; mt < 2; mt++)
#pragma unroll
                for (int nt = 0; nt < 8; nt++)
                    mma_tf32(c[mt][nt], a[mt], b[nt]);
        }

        if (cc < 15) {
            int nxt = cur ^ 1;
#pragma unroll
            for (int q = 0; q < 4; q++) {
                As[nxt][sa_kq + q * 4 + 0][sa_m] = f2tf32(pa[q].x);
                As[nxt][sa_kq + q * 4 + 1][sa_m] = f2tf32(pa[q].y);
                As[nxt][sa_kq + q * 4 + 2][sa_m] = f2tf32(pa[q].z);
                As[nxt][sa_kq + q * 4 + 3][sa_m] = f2tf32(pa[q].w);
                uint4 u;
                u.x = f2tf32(pb[q].x); u.y = f2tf32(pb[q].y);
                u.z = f2tf32(pb[q].z); u.w = f2tf32(pb[q].w);
                *(uint4*)&Bs[nxt][sb_k][sb_n + q * 4] = u;
            }
            __syncthreads();
        }
    }

    // epilogue
    int seg = c_seg[e];
#pragma unroll
    for (int mt = 0; mt < 2; mt++) {
        int r0   = wm + mt * 16 + grp;
        int tok0 = s_tok[r0];
        int tok1 = s_tok[r0 + 8];
        if (tok0 >= 0) {
            float* o = p.out + (size_t)tok0 * OUTW + seg + n0 + wn + 2 * th4;
#pragma unroll
            for (int nt = 0; nt < 8; nt++)
                *(float2*)(o + nt * 8) = make_float2(c[mt][nt][0], c[mt][nt][1]);
        }
        if (tok1 >= 0) {
            float* o = p.out + (size_t)tok1 * OUTW + seg + n0 + wn + 2 * th4;
#pragma unroll
            for (int nt = 0; nt < 8; nt++)
                *(float2*)(o + nt * 8) = make_float2(c[mt][nt][2], c[mt][nt][3]);
        }
    }
}

// ---------------- host launcher ---------------------------------------------------
extern "C" void kernel_launch(void* const* d_in, const int* in_sizes, int n_in,
                              void* d_out, int out_size) {
    (void)in_sizes; (void)n_in; (void)out_size;
    // input order (setup_inputs dict order):
    // 0:A 1:X 2:Y 3:SP 4:P 5:PCH 6:PCL 7:Op 8:Val 9:fu_map
    // 10..24: (emb, W1, b1) x {alu, logic, move, flow, stack}
    // 25:alu_Wr 26:alu_Wf 27:logic_Wr 28:logic_Wf 29:move_Wo 30:flow_Wo 31:stack_Wo
    cudaFuncSetAttribute(precompute_T,
                         cudaFuncAttributeMaxDynamicSharedMemorySize, PT_SMEM);
    cudaFuncSetAttribute(gemm2_kernel,
                         cudaFuncAttributeMaxDynamicSharedMemorySize, G2_SMEM);

    PTP pt;
    HP  hp;
    for (int i = 0; i < 9; i++) hp.base[i] = (const int*)d_in[i];
    for (int e = 0; e < 5; e++) {
        pt.emb[e] = (const float*)d_in[10 + 3 * e];
        pt.W1[e]  = (const float*)d_in[11 + 3 * e];
        hp.b1[e]  = (const float*)d_in[12 + 3 * e];
    }
    FP fp;
    fp.Wf[0] = (const float*)d_in[26];
    fp.Wf[1] = (const float*)d_in[28];
    fp.out   = (float*)d_out;

    G2P p2;
    p2.out  = (float*)d_out;
    p2.B[0] = (const float*)d_in[25];
    p2.B[1] = (const float*)d_in[27];
    p2.B[2] = (const float*)d_in[29];
    p2.B[3] = (const float*)d_in[30];
    p2.B[4] = (const float*)d_in[31];

    const int* Op = (const int*)d_in[7];
    const int* fu = (const int*)d_in[9];

    // counts are zero at module load; reset_counts restores the invariant
    // at the end of every call (incl. correctness run and each graph replay).
    compact_kernel<<<NTOK / 256, 256>>>(Op, fu);              // launch 0
    precompute_T<<<dim3(4, 4, 30), 256, PT_SMEM>>>(pt);       // launch 1
    h_kernel<<<dim3(1024, 5), 256>>>(hp);                     // launch 2
    gemm2_kernel<<<dim3(512, 2, 5), 256, G2_SMEM>>>(p2);      // launch 3 (profiled)
    flag_kernel<<<dim3(2048, 2), 256>>>(fp);                  // launch 4
    reset_counts<<<1, 32>>>();                                // launch 5
}

// round 11
// speedup vs baseline: 1.5407x; 1.1708x over previous
#include <cuda_runtime.h>
#include <cstdint>
#include <cstddef>

// ============================================================================
// Swarm6502 masked 5-expert MoE. R11:
//  - operands pre-rounded to tf32 (h_kernel output; B matrices via compact grid)
//  - gemm2 v4: cp.async.cg 3-stage pipeline, BK=16, no reg staging / cvt in loop,
//    one barrier per chunk; grid (n0 inner) for A L2 reuse.
// Pipeline: compact(+cvtB) -> precompute_T -> h -> gemm2 -> flag -> reset
// ============================================================================

#define NTOK 65536
#define HDIM 512
#define OUTW 1296
#define BK   16
#define ASP  20    // As row stride (words): bank=(4m+k)%32 bijective per warp
#define BSP  132   // Bs row stride (words): bank=(4k+n)%32 bijective per warp

__device__ int   g_counts[5];                        // zero-init at load
__device__ int   g_lists[5][NTOK];
__device__ float g_H[(size_t)NTOK * HDIM];           // tf32-rounded hidden
__device__ float g_T[(size_t)5 * 6 * 256 * HDIM];    // lookup tables
__device__ float g_Btf[5 * HDIM * 256];              // tf32-rounded B matrices

// index source codes: 0=A 1=X 2=Y 3=SP 4=P 5=PCH 6=PCL 7=Op 8=Val 9=carry(P&1)
__constant__ int c_code[5][6] = {
    {0, 8, 9, 7, -1, -1},   // alu
    {0, 8, 9, 7, -1, -1},   // logic
    {0, 1, 2, 8, 7, -1},    // move
    {5, 6, 4, 8, 3, 7},     // flow
    {0, 1, 3, 4, 8, 7}      // stack
};
__constant__ int c_k[5]    = {4, 4, 5, 6, 6};
__constant__ int c_nout[5] = {264, 264, 256, 256, 256};
__constant__ int c_seg[5]  = {0, 264, 528, 784, 1040};

struct PTP { const float* emb[5]; const float* W1[5]; };
struct HP  { const int* base[9]; const float* b1[5]; };
struct FP  { const float* Wf[2]; float* out; };
struct CP  { const float* B[5]; };
struct G2P { float* out; };

__device__ __forceinline__ float gelu_tanh(float x) {
    float x3 = x * x * x;
    float t  = tanhf(0.7978845608028654f * (x + 0.044715f * x3));
    return 0.5f * x * (1.0f + t);
}
__device__ __forceinline__ uint32_t f2tf32(float x) {
    uint32_t r;
    asm("cvt.rna.tf32.f32 %0, %1;" : "=r"(r) : "f"(x));
    return r;
}
__device__ __forceinline__ void mma_tf32(float* c, const uint32_t* a,
                                         const uint32_t* b) {
    asm volatile(
        "mma.sync.aligned.m16n8k8.row.col.f32.tf32.tf32.f32 "
        "{%0,%1,%2,%3}, {%4,%5,%6,%7}, {%8,%9}, {%0,%1,%2,%3};"
        : "+f"(c[0]), "+f"(c[1]), "+f"(c[2]), "+f"(c[3])
        : "r"(a[0]), "r"(a[1]), "r"(a[2]), "r"(a[3]), "r"(b[0]), "r"(b[1]));
}
#define CP_ASYNC_CG(dst, src, sz) \
    asm volatile("cp.async.cg.shared.global [%0], [%1], 16, %2;" \
                 :: "r"(dst), "l"(src), "r"(sz))
#define CP_COMMIT() asm volatile("cp.async.commit_group;")
#define CP_WAIT1()  asm volatile("cp.async.wait_group 1;")

// ---------------- compact + cvtB (one launch; counts zero on entry) -------------
__global__ void compact_kernel(const int* __restrict__ Op,
                               const int* __restrict__ fu_map, CP p) {
    long gid = (long)blockIdx.x * blockDim.x + threadIdx.x;
    if (gid < NTOK) {
        int e   = fu_map[Op[gid]];
        int pos = atomicAdd(&g_counts[e], 1);
        g_lists[e][pos] = (int)gid;
    } else {
        long i = gid - NTOK;                 // 0 .. 5*131072-1
        if (i < 5L * HDIM * 256) {
            int e = (int)(i >> 17);
            int r = (int)(i & (HDIM * 256 - 1));
            g_Btf[i] = __uint_as_float(f2tf32(__ldg(p.B[e] + r)));
        }
    }
}
__global__ void reset_counts() {
    if (threadIdx.x < 5) g_counts[threadIdx.x] = 0;
}

// ---------------- precompute T[e][j] = emb_ej @ W1_ej ---------------------------
#define PT_SMEM ((64 * 65 + 64 * 128) * 4)
__global__ void __launch_bounds__(256) precompute_T(PTP p) {
    int z = blockIdx.z, e = z / 6, j = z % 6;
    if (j >= c_k[e]) return;
    int v0 = blockIdx.x * 64;
    int n0 = blockIdx.y * 128;

    extern __shared__ float smp[];
    float (*Es)[65]  = (float(*)[65])smp;
    float (*Ws)[128] = (float(*)[128])(smp + 64 * 65);
    int tid = threadIdx.x;

    {
        int r = tid >> 2, c = (tid & 3) * 16;
        const float* src = p.emb[e] + ((size_t)j * 256 + v0 + r) * 64 + c;
#pragma unroll
        for (int q = 0; q < 16; q++) Es[r][c + q] = __ldg(src + q);
    }
    {
        int r = tid >> 2, c0 = (tid & 3) * 32;
        const float4* src =
            (const float4*)(p.W1[e] + ((size_t)(j * 64 + r)) * HDIM + n0 + c0);
        float4* dst = (float4*)&Ws[r][c0];
#pragma unroll
        for (int q = 0; q < 8; q++) dst[q] = __ldg(src + q);
    }
    __syncthreads();

    float acc[4][8];
#pragma unroll
    for (int i = 0; i < 4; i++)
#pragma unroll
        for (int jj = 0; jj < 8; jj++) acc[i][jj] = 0.f;

    int tm = (tid >> 4) * 4, tn = (tid & 15) * 8;
#pragma unroll
    for (int k = 0; k < 64; k++) {
        float a[4], b[8];
#pragma unroll
        for (int i = 0; i < 4; i++) a[i] = Es[tm + i][k];
        float4 b0 = *(const float4*)&Ws[k][tn];
        float4 b1 = *(const float4*)&Ws[k][tn + 4];
        b[0] = b0.x; b[1] = b0.y; b[2] = b0.z; b[3] = b0.w;
        b[4] = b1.x; b[5] = b1.y; b[6] = b1.z; b[7] = b1.w;
#pragma unroll
        for (int i = 0; i < 4; i++)
#pragma unroll
            for (int jj = 0; jj < 8; jj++)
                acc[i][jj] = fmaf(a[i], b[jj], acc[i][jj]);
    }

    float* T = g_T + ((size_t)(e * 6 + j) * 256) * HDIM;
#pragma unroll
    for (int i = 0; i < 4; i++) {
        float* d = T + (size_t)(v0 + tm + i) * HDIM + n0 + tn;
        *(float4*)d       = make_float4(acc[i][0], acc[i][1], acc[i][2], acc[i][3]);
        *(float4*)(d + 4) = make_float4(acc[i][4], acc[i][5], acc[i][6], acc[i][7]);
    }
}

// ---------------- h = tf32(gelu(sum_j T[e][j][idx_j] + b1)) ---------------------
__global__ void __launch_bounds__(256) h_kernel(HP p) {
    int e  = blockIdx.y;
    int C  = g_counts[e];
    int m0 = blockIdx.x * 64;
    if (m0 >= C) return;

    int tid = threadIdx.x;
    int g   = tid >> 7, t = tid & 127;
    int kc  = c_k[e];
    float4 bias = __ldg((const float4*)p.b1[e] + t);
    const float* Tb = g_T + ((size_t)(e * 6) << 17);

    int mEnd = m0 + 64;
    if (mEnd > C) mEnd = C;
    int mi = m0 + g;
    for (; mi + 2 < mEnd; mi += 4) {
        int tok0 = g_lists[e][mi];
        int tok1 = g_lists[e][mi + 2];
        float4 a0 = bias, a1 = bias;
        for (int j = 0; j < kc; j++) {
            int code = c_code[e][j];
            int i0 = (code == 9) ? (__ldg(p.base[4] + tok0) & 1)
                                 : __ldg(p.base[code] + tok0);
            int i1 = (code == 9) ? (__ldg(p.base[4] + tok1) & 1)
                                 : __ldg(p.base[code] + tok1);
            float4 v0 = ((const float4*)(Tb + (((size_t)j * 256 + i0) << 9)))[t];
            float4 v1 = ((const float4*)(Tb + (((size_t)j * 256 + i1) << 9)))[t];
            a0.x += v0.x; a0.y += v0.y; a0.z += v0.z; a0.w += v0.w;
            a1.x += v1.x; a1.y += v1.y; a1.z += v1.z; a1.w += v1.w;
        }
        float4 o0, o1;
        o0.x = __uint_as_float(f2tf32(gelu_tanh(a0.x)));
        o0.y = __uint_as_float(f2tf32(gelu_tanh(a0.y)));
        o0.z = __uint_as_float(f2tf32(gelu_tanh(a0.z)));
        o0.w = __uint_as_float(f2tf32(gelu_tanh(a0.w)));
        o1.x = __uint_as_float(f2tf32(gelu_tanh(a1.x)));
        o1.y = __uint_as_float(f2tf32(gelu_tanh(a1.y)));
        o1.z = __uint_as_float(f2tf32(gelu_tanh(a1.z)));
        o1.w = __uint_as_float(f2tf32(gelu_tanh(a1.w)));
        ((float4*)(g_H + ((size_t)tok0 << 9)))[t] = o0;
        ((float4*)(g_H + ((size_t)tok1 << 9)))[t] = o1;
    }
    for (; mi < mEnd; mi += 2) {
        int tok = g_lists[e][mi];
        float4 acc = bias;
        for (int j = 0; j < kc; j++) {
            int code = c_code[e][j];
            int idx  = (code == 9) ? (__ldg(p.base[4] + tok) & 1)
                                   : __ldg(p.base[code] + tok);
            float4 v = ((const float4*)(Tb + (((size_t)j * 256 + idx) << 9)))[t];
            acc.x += v.x; acc.y += v.y; acc.z += v.z; acc.w += v.w;
        }
        float4 r;
        r.x = __uint_as_float(f2tf32(gelu_tanh(acc.x)));
        r.y = __uint_as_float(f2tf32(gelu_tanh(acc.y)));
        r.z = __uint_as_float(f2tf32(gelu_tanh(acc.z)));
        r.w = __uint_as_float(f2tf32(gelu_tanh(acc.w)));
        ((float4*)(g_H + ((size_t)tok << 9)))[t] = r;
    }
}

// ---------------- flag cols (alu/logic); h is tf32-rounded (error << budget) ----
__global__ void __launch_bounds__(256) flag_kernel(FP p) {
    int e  = blockIdx.y;
    int C  = g_counts[e];
    int m0 = blockIdx.x * 32;
    if (m0 >= C) return;

    __shared__ float sWf[HDIM][8];
    int tid = threadIdx.x;
    const float4* Wf4 = (const float4*)p.Wf[e];
#pragma unroll
    for (int i = 0; i < 4; i++)
        ((float4*)sWf)[tid + i * 256] = __ldg(Wf4 + tid + i * 256);
    __syncthreads();

    int r = tid >> 3, f = tid & 7;
    int mi = m0 + r;
    if (mi >= C) return;
    int tok = g_lists[e][mi];
    const float4* h = (const float4*)(g_H + ((size_t)tok << 9));
    float dot = 0.f;
#pragma unroll 4
    for (int k4 = 0; k4 < 128; k4++) {
        float4 hv = __ldg(h + k4);
        dot += hv.x * sWf[k4 * 4 + 0][f];
        dot += hv.y * sWf[k4 * 4 + 1][f];
        dot += hv.z * sWf[k4 * 4 + 2][f];
        dot += hv.w * sWf[k4 * 4 + 3][f];
    }
    p.out[(size_t)tok * OUTW + c_seg[e] + 256 + f] = dot;
}

// ---------------- gemm2 v4: cp.async 3-stage tf32 MMA ---------------------------
// (C x 512) @ (512 x 256). BM=128, BN=128, BK=16, 32 chunks, 3 stages.
// grid (2, 512, 5): n0 inner -> the two n-halves share A tile via L2.
#define G2_SMEM (3 * (128 * ASP + BK * BSP) * 4)
__global__ void __launch_bounds__(256) gemm2_kernel(G2P p) {
    int e  = blockIdx.z;
    int C  = g_counts[e];
    int m0 = blockIdx.y * 128;
    if (m0 >= C) return;
    int n0 = blockIdx.x * 128;

    extern __shared__ uint32_t smg[];
    uint32_t (*As)[ASP] = (uint32_t(*)[ASP])smg;                 // [3*128][ASP]
    uint32_t (*Bs)[BSP] = (uint32_t(*)[BSP])(smg + 3 * 128 * ASP); // [3*BK][BSP]
    __shared__ int s_tok[128];

    int tid = threadIdx.x;
    if (tid < 128) {
        int m = m0 + tid;
        s_tok[tid] = (m < C) ? g_lists[e][m] : -1;
    }
    __syncthreads();

    // zero-fill complement of the 1296-wide rows (n0==0 blocks only)
    if (blockIdx.x == 0) {
        int s4 = c_seg[e] >> 2;
        int e4 = (c_seg[e] + c_nout[e]) >> 2;
        float4* out4 = (float4*)p.out;
        float4 z = make_float4(0.f, 0.f, 0.f, 0.f);
        for (int u = tid; u < 128 * (OUTW / 4); u += 256) {
            int m = u / (OUTW / 4);
            int f = u - m * (OUTW / 4);
            if (f >= s4 && f < e4) continue;
            int tok = s_tok[m];
            if (tok < 0) continue;
            out4[(size_t)tok * (OUTW / 4) + f] = z;
        }
    }

    // ---- staging assignments (fixed per thread) ----
    int ar0 = tid >> 2;              // rows 0..63
    int ar1 = 64 + ar0;              // rows 64..127
    int akq = (tid & 3) * 4;         // k-quad within chunk
    int tokA0 = s_tok[ar0], tokA1 = s_tok[ar1];
    const float* srcA0 = g_H + ((size_t)(tokA0 < 0 ? 0 : tokA0) << 9) + akq;
    const float* srcA1 = g_H + ((size_t)(tokA1 < 0 ? 0 : tokA1) << 9) + akq;
    int szA0 = (tokA0 < 0) ? 0 : 16;
    int szA1 = (tokA1 < 0) ? 0 : 16;
    int bk0 = tid >> 5;              // 0..7   (B k-rows; +8 for second)
    int bn0 = (tid & 31) * 4;        // 0..124
    const float* __restrict__ Bg = g_Btf + ((size_t)e * HDIM * 256);

    uint32_t sbase = (uint32_t)__cvta_generic_to_shared(smg);
    const uint32_t BOFF = 3 * 128 * ASP * 4;   // byte offset of Bs

    // stage chunk cc into stage st
    auto stage = [&](int st, int cc) {
        int kk = cc * BK;
        uint32_t dA0 = sbase + ((st * 128 + ar0) * ASP + akq) * 4;
        uint32_t dA1 = sbase + ((st * 128 + ar1) * ASP + akq) * 4;
        CP_ASYNC_CG(dA0, srcA0 + kk, szA0);
        CP_ASYNC_CG(dA1, srcA1 + kk, szA1);
        uint32_t dB0 = sbase + BOFF + ((st * BK + bk0) * BSP + bn0) * 4;
        uint32_t dB1 = sbase + BOFF + ((st * BK + bk0 + 8) * BSP + bn0) * 4;
        CP_ASYNC_CG(dB0, Bg + (size_t)(kk + bk0) * 256 + n0 + bn0, 16);
        CP_ASYNC_CG(dB1, Bg + (size_t)(kk + bk0 + 8) * 256 + n0 + bn0, 16);
    };

    int lane = tid & 31, wrp = tid >> 5;
    int wm = (wrp & 3) * 32;
    int wn = (wrp >> 2) * 64;
    int grp = lane >> 2, th4 = lane & 3;

    float c[2][8][4];
#pragma unroll
    for (int mt = 0; mt < 2; mt++)
#pragma unroll
        for (int nt = 0; nt < 8; nt++)
#pragma unroll
            for (int i = 0; i < 4; i++) c[mt][nt][i] = 0.f;

    stage(0, 0); CP_COMMIT();
    stage(1, 1); CP_COMMIT();

    int cur = 0;
    for (int cc = 0; cc < 32; cc++) {
        CP_WAIT1();
        __syncthreads();

        int ab = cur * 128;
        int bb = cur * BK;
#pragma unroll
        for (int k8 = 0; k8 < BK; k8 += 8) {
            int kb = k8 + th4;
            uint32_t a[2][4], b[8][2];
#pragma unroll
            for (int mt = 0; mt < 2; mt++) {
                int mb = ab + wm + mt * 16;
                a[mt][0] = As[mb + grp][kb];
                a[mt][1] = As[mb + 8 + grp][kb];
                a[mt][2] = As[mb + grp][kb + 4];
                a[mt][3] = As[mb + 8 + grp][kb + 4];
            }
#pragma unroll
            for (int nt = 0; nt < 8; nt++) {
                b[nt][0] = Bs[bb + kb][wn + nt * 8 + grp];
                b[nt][1] = Bs[bb + kb + 4][wn + nt * 8 + grp];
            }
#pragma unroll
            for (int mt = 0; mt < 2; mt++)
#pragma unroll
                for (int nt = 0; nt < 8; nt++)
                    mma_tf32(c[mt][nt], a[mt], b[nt]);
        }

        // stage chunk cc+2 into the stage that held chunk cc-1 (all warps are
        // past its MMA: the barrier above orders iteration cc-1 completion).
        if (cc + 2 < 32) {
            int st = cur + 2; if (st >= 3) st -= 3;
            stage(st, cc + 2);
        }
        CP_COMMIT();
        if (++cur == 3) cur = 0;
    }

    // epilogue
    int seg = c_seg[e];
#pragma unroll
    for (int mt = 0; mt < 2; mt++) {
        int r0   = wm + mt * 16 + grp;
        int tok0 = s_tok[r0];
        int tok1 = s_tok[r0 + 8];
        if (tok0 >= 0) {
            float* o = p.out + (size_t)tok0 * OUTW + seg + n0 + wn + 2 * th4;
#pragma unroll
            for (int nt = 0; nt < 8; nt++)
                *(float2*)(o + nt * 8) = make_float2(c[mt][nt][0], c[mt][nt][1]);
        }
        if (tok1 >= 0) {
            float* o = p.out + (size_t)tok1 * OUTW + seg + n0 + wn + 2 * th4;
#pragma unroll
            for (int nt = 0; nt < 8; nt++)
                *(float2*)(o + nt * 8) = make_float2(c[mt][nt][2], c[mt][nt][3]);
        }
    }
}

// ---------------- host launcher ---------------------------------------------------
extern "C" void kernel_launch(void* const* d_in, const int* in_sizes, int n_in,
                              void* d_out, int out_size) {
    (void)in_sizes; (void)n_in; (void)out_size;
    // input order (setup_inputs dict order):
    // 0:A 1:X 2:Y 3:SP 4:P 5:PCH 6:PCL 7:Op 8:Val 9:fu_map
    // 10..24: (emb, W1, b1) x {alu, logic, move, flow, stack}
    // 25:alu_Wr 26:alu_Wf 27:logic_Wr 28:logic_Wf 29:move_Wo 30:flow_Wo 31:stack_Wo
    cudaFuncSetAttribute(precompute_T,
                         cudaFuncAttributeMaxDynamicSharedMemorySize, PT_SMEM);
    cudaFuncSetAttribute(gemm2_kernel,
                         cudaFuncAttributeMaxDynamicSharedMemorySize, G2_SMEM);

    PTP pt;
    HP  hp;
    for (int i = 0; i < 9; i++) hp.base[i] = (const int*)d_in[i];
    for (int e = 0; e < 5; e++) {
        pt.emb[e] = (const float*)d_in[10 + 3 * e];
        pt.W1[e]  = (const float*)d_in[11 + 3 * e];
        hp.b1[e]  = (const float*)d_in[12 + 3 * e];
    }
    FP fp;
    fp.Wf[0] = (const float*)d_in[26];
    fp.Wf[1] = (const float*)d_in[28];
    fp.out   = (float*)d_out;

    CP cp;
    cp.B[0] = (const float*)d_in[25];
    cp.B[1] = (const float*)d_in[27];
    cp.B[2] = (const float*)d_in[29];
    cp.B[3] = (const float*)d_in[30];
    cp.B[4] = (const float*)d_in[31];

    G2P p2;
    p2.out = (float*)d_out;

    const int* Op = (const int*)d_in[7];
    const int* fu = (const int*)d_in[9];

    // counts zero at load; reset_counts restores invariant every call.
    int nblk = (NTOK + 5 * HDIM * 256) / 256;                 // compaction + cvtB
    compact_kernel<<<nblk, 256>>>(Op, fu, cp);                // launch 0
    precompute_T<<<dim3(4, 4, 30), 256, PT_SMEM>>>(pt);       // launch 1
    h_kernel<<<dim3(1024, 5), 256>>>(hp);                     // launch 2
    gemm2_kernel<<<dim3(2, 512, 5), 256, G2_SMEM>>>(p2);      // launch 3 (profiled)
    flag_kernel<<<dim3(2048, 2), 256>>>(fp);                  // launch 4
    reset_counts<<<1, 32>>>();                                // launch 5
}

// round 12
// speedup vs baseline: 1.6861x; 1.0944x over previous
#include <cuda_runtime.h>
#include <cstdint>
#include <cstddef>

// ============================================================================
// Swarm6502 masked 5-expert MoE. R12:
//  - gemm2 v5: BN=64 warp tile 32x32 -> 32 accum regs -> 3 blocks/SM (24 warps);
//    conflict-free smem (ASP=20, BSP=72); cp.async 3-stage; n0-inner A L2 reuse.
//  - h_kernel v2: indices pre-staged in smem -> independent row gathers.
// Pipeline: compact(+cvtB) -> precompute_T -> h -> gemm2 -> flag -> reset
// ============================================================================

#define NTOK 65536
#define HDIM 512
#define OUTW 1296
#define BK   16
#define ASP  20    // As row stride: bank=(20m+k)%32 bijective per warp
#define BSP  72    // Bs row stride: bank=(8k+n)%32 bijective per warp

__device__ int   g_counts[5];                        // zero-init at load
__device__ int   g_lists[5][NTOK];
__device__ float g_H[(size_t)NTOK * HDIM];           // tf32-rounded hidden
__device__ float g_T[(size_t)5 * 6 * 256 * HDIM];    // lookup tables
__device__ float g_Btf[5 * HDIM * 256];              // tf32-rounded B matrices

// index source codes: 0=A 1=X 2=Y 3=SP 4=P 5=PCH 6=PCL 7=Op 8=Val 9=carry(P&1)
__constant__ int c_code[5][6] = {
    {0, 8, 9, 7, -1, -1},   // alu
    {0, 8, 9, 7, -1, -1},   // logic
    {0, 1, 2, 8, 7, -1},    // move
    {5, 6, 4, 8, 3, 7},     // flow
    {0, 1, 3, 4, 8, 7}      // stack
};
__constant__ int c_k[5]    = {4, 4, 5, 6, 6};
__constant__ int c_nout[5] = {264, 264, 256, 256, 256};
__constant__ int c_seg[5]  = {0, 264, 528, 784, 1040};

struct PTP { const float* emb[5]; const float* W1[5]; };
struct HP  { const int* base[9]; const float* b1[5]; };
struct FP  { const float* Wf[2]; float* out; };
struct CP  { const float* B[5]; };
struct G2P { float* out; };

__device__ __forceinline__ float gelu_tanh(float x) {
    float x3 = x * x * x;
    float t  = tanhf(0.7978845608028654f * (x + 0.044715f * x3));
    return 0.5f * x * (1.0f + t);
}
__device__ __forceinline__ uint32_t f2tf32(float x) {
    uint32_t r;
    asm("cvt.rna.tf32.f32 %0, %1;" : "=r"(r) : "f"(x));
    return r;
}
__device__ __forceinline__ void mma_tf32(float* c, const uint32_t* a,
                                         const uint32_t* b) {
    asm volatile(
        "mma.sync.aligned.m16n8k8.row.col.f32.tf32.tf32.f32 "
        "{%0,%1,%2,%3}, {%4,%5,%6,%7}, {%8,%9}, {%0,%1,%2,%3};"
        : "+f"(c[0]), "+f"(c[1]), "+f"(c[2]), "+f"(c[3])
        : "r"(a[0]), "r"(a[1]), "r"(a[2]), "r"(a[3]), "r"(b[0]), "r"(b[1]));
}
#define CP_ASYNC_CG(dst, src, sz) \
    asm volatile("cp.async.cg.shared.global [%0], [%1], 16, %2;" \
                 :: "r"(dst), "l"(src), "r"(sz))
#define CP_COMMIT() asm volatile("cp.async.commit_group;")
#define CP_WAIT1()  asm volatile("cp.async.wait_group 1;")

// ---------------- compact + cvtB (one launch; counts zero on entry) -------------
__global__ void compact_kernel(const int* __restrict__ Op,
                               const int* __restrict__ fu_map, CP p) {
    long gid = (long)blockIdx.x * blockDim.x + threadIdx.x;
    if (gid < NTOK) {
        int e   = fu_map[Op[gid]];
        int pos = atomicAdd(&g_counts[e], 1);
        g_lists[e][pos] = (int)gid;
    } else {
        long i = gid - NTOK;                 // 0 .. 5*131072-1
        if (i < 5L * HDIM * 256) {
            int e = (int)(i >> 17);
            int r = (int)(i & (HDIM * 256 - 1));
            g_Btf[i] = __uint_as_float(f2tf32(__ldg(p.B[e] + r)));
        }
    }
}
__global__ void reset_counts() {
    if (threadIdx.x < 5) g_counts[threadIdx.x] = 0;
}

// ---------------- precompute T[e][j] = emb_ej @ W1_ej ---------------------------
#define PT_SMEM ((64 * 65 + 64 * 128) * 4)
__global__ void __launch_bounds__(256) precompute_T(PTP p) {
    int z = blockIdx.z, e = z / 6, j = z % 6;
    if (j >= c_k[e]) return;
    int v0 = blockIdx.x * 64;
    int n0 = blockIdx.y * 128;

    extern __shared__ float smp[];
    float (*Es)[65]  = (float(*)[65])smp;
    float (*Ws)[128] = (float(*)[128])(smp + 64 * 65);
    int tid = threadIdx.x;

    {
        int r = tid >> 2, c = (tid & 3) * 16;
        const float* src = p.emb[e] + ((size_t)j * 256 + v0 + r) * 64 + c;
#pragma unroll
        for (int q = 0; q < 16; q++) Es[r][c + q] = __ldg(src + q);
    }
    {
        int r = tid >> 2, c0 = (tid & 3) * 32;
        const float4* src =
            (const float4*)(p.W1[e] + ((size_t)(j * 64 + r)) * HDIM + n0 + c0);
        float4* dst = (float4*)&Ws[r][c0];
#pragma unroll
        for (int q = 0; q < 8; q++) dst[q] = __ldg(src + q);
    }
    __syncthreads();

    float acc[4][8];
#pragma unroll
    for (int i = 0; i < 4; i++)
#pragma unroll
        for (int jj = 0; jj < 8; jj++) acc[i][jj] = 0.f;

    int tm = (tid >> 4) * 4, tn = (tid & 15) * 8;
#pragma unroll
    for (int k = 0; k < 64; k++) {
        float a[4], b[8];
#pragma unroll
        for (int i = 0; i < 4; i++) a[i] = Es[tm + i][k];
        float4 b0 = *(const float4*)&Ws[k][tn];
        float4 b1 = *(const float4*)&Ws[k][tn + 4];
        b[0] = b0.x; b[1] = b0.y; b[2] = b0.z; b[3] = b0.w;
        b[4] = b1.x; b[5] = b1.y; b[6] = b1.z; b[7] = b1.w;
#pragma unroll
        for (int i = 0; i < 4; i++)
#pragma unroll
            for (int jj = 0; jj < 8; jj++)
                acc[i][jj] = fmaf(a[i], b[jj], acc[i][jj]);
    }

    float* T = g_T + ((size_t)(e * 6 + j) * 256) * HDIM;
#pragma unroll
    for (int i = 0; i < 4; i++) {
        float* d = T + (size_t)(v0 + tm + i) * HDIM + n0 + tn;
        *(float4*)d       = make_float4(acc[i][0], acc[i][1], acc[i][2], acc[i][3]);
        *(float4*)(d + 4) = make_float4(acc[i][4], acc[i][5], acc[i][6], acc[i][7]);
    }
}

// ---------------- h v2: smem-staged indices -> independent gathers ---------------
__global__ void __launch_bounds__(256) h_kernel(HP p) {
    int e  = blockIdx.y;
    int C  = g_counts[e];
    int m0 = blockIdx.x * 64;
    if (m0 >= C) return;

    __shared__ int s_tok[64];
    __shared__ int s_idx[6][64];

    int tid = threadIdx.x;
    int kc  = c_k[e];
    if (tid < 64) {
        int m = m0 + tid;
        s_tok[tid] = (m < C) ? g_lists[e][m] : -1;
    }
    __syncthreads();
    for (int u = tid; u < kc * 64; u += 256) {
        int j = u >> 6, m = u & 63;
        int tok = s_tok[m];
        int idx = 0;
        if (tok >= 0) {
            int code = c_code[e][j];
            idx = (code == 9) ? (__ldg(p.base[4] + tok) & 1)
                              : __ldg(p.base[code] + tok);
        }
        s_idx[j][m] = idx;
    }
    __syncthreads();

    int g = tid >> 7, t = tid & 127;
    float4 bias = __ldg((const float4*)p.b1[e] + t);
    const float* Tb = g_T + ((size_t)(e * 6) << 17);

    for (int lm = g * 32; lm < g * 32 + 32; lm += 2) {
        int tok0 = s_tok[lm], tok1 = s_tok[lm + 1];
        if (tok0 < 0) continue;     // list is dense: tok1<0 possible only at tail
        float4 a0 = bias, a1 = bias;
        for (int j = 0; j < kc; j++) {
            float4 v0 = ((const float4*)(
                Tb + (((size_t)j * 256 + s_idx[j][lm]) << 9)))[t];
            a0.x += v0.x; a0.y += v0.y; a0.z += v0.z; a0.w += v0.w;
            if (tok1 >= 0) {
                float4 v1 = ((const float4*)(
                    Tb + (((size_t)j * 256 + s_idx[j][lm + 1]) << 9)))[t];
                a1.x += v1.x; a1.y += v1.y; a1.z += v1.z; a1.w += v1.w;
            }
        }
        float4 o0;
        o0.x = __uint_as_float(f2tf32(gelu_tanh(a0.x)));
        o0.y = __uint_as_float(f2tf32(gelu_tanh(a0.y)));
        o0.z = __uint_as_float(f2tf32(gelu_tanh(a0.z)));
        o0.w = __uint_as_float(f2tf32(gelu_tanh(a0.w)));
        ((float4*)(g_H + ((size_t)tok0 << 9)))[t] = o0;
        if (tok1 >= 0) {
            float4 o1;
            o1.x = __uint_as_float(f2tf32(gelu_tanh(a1.x)));
            o1.y = __uint_as_float(f2tf32(gelu_tanh(a1.y)));
            o1.z = __uint_as_float(f2tf32(gelu_tanh(a1.z)));
            o1.w = __uint_as_float(f2tf32(gelu_tanh(a1.w)));
            ((float4*)(g_H + ((size_t)tok1 << 9)))[t] = o1;
        }
    }
}

// ---------------- flag cols (alu/logic) ------------------------------------------
__global__ void __launch_bounds__(256) flag_kernel(FP p) {
    int e  = blockIdx.y;
    int C  = g_counts[e];
    int m0 = blockIdx.x * 32;
    if (m0 >= C) return;

    __shared__ float sWf[HDIM][8];
    int tid = threadIdx.x;
    const float4* Wf4 = (const float4*)p.Wf[e];
#pragma unroll
    for (int i = 0; i < 4; i++)
        ((float4*)sWf)[tid + i * 256] = __ldg(Wf4 + tid + i * 256);
    __syncthreads();

    int r = tid >> 3, f = tid & 7;
    int mi = m0 + r;
    if (mi >= C) return;
    int tok = g_lists[e][mi];
    const float4* h = (const float4*)(g_H + ((size_t)tok << 9));
    float dot = 0.f;
#pragma unroll 4
    for (int k4 = 0; k4 < 128; k4++) {
        float4 hv = __ldg(h + k4);
        dot += hv.x * sWf[k4 * 4 + 0][f];
        dot += hv.y * sWf[k4 * 4 + 1][f];
        dot += hv.z * sWf[k4 * 4 + 2][f];
        dot += hv.w * sWf[k4 * 4 + 3][f];
    }
    p.out[(size_t)tok * OUTW + c_seg[e] + 256 + f] = dot;
}

// ---------------- gemm2 v5: BN=64, 3 blocks/SM, cp.async 3-stage tf32 MMA --------
// (C x 512) @ (512 x 256). BM=128, BN=64, BK=16, 32 chunks, 3 stages, 8 warps.
// warp tile 32x32. grid (4, 512, 5): n0 inner -> A tile L2-shared by 4 blocks.
#define G2_SMEM (3 * (128 * ASP + BK * BSP) * 4)
__global__ void __launch_bounds__(256, 3) gemm2_kernel(G2P p) {
    int e  = blockIdx.z;
    int C  = g_counts[e];
    int m0 = blockIdx.y * 128;
    if (m0 >= C) return;
    int n0 = blockIdx.x * 64;

    extern __shared__ uint32_t smg[];
    uint32_t (*As)[ASP] = (uint32_t(*)[ASP])smg;                   // [3*128][ASP]
    uint32_t (*Bs)[BSP] = (uint32_t(*)[BSP])(smg + 3 * 128 * ASP); // [3*BK][BSP]
    __shared__ int s_tok[128];

    int tid = threadIdx.x;
    if (tid < 128) {
        int m = m0 + tid;
        s_tok[tid] = (m < C) ? g_lists[e][m] : -1;
    }
    __syncthreads();

    // zero-fill complement of the 1296-wide rows (n0==0 blocks only)
    if (blockIdx.x == 0) {
        int s4 = c_seg[e] >> 2;
        int e4 = (c_seg[e] + c_nout[e]) >> 2;
        float4* out4 = (float4*)p.out;
        float4 z = make_float4(0.f, 0.f, 0.f, 0.f);
        for (int u = tid; u < 128 * (OUTW / 4); u += 256) {
            int m = u / (OUTW / 4);
            int f = u - m * (OUTW / 4);
            if (f >= s4 && f < e4) continue;
            int tok = s_tok[m];
            if (tok < 0) continue;
            out4[(size_t)tok * (OUTW / 4) + f] = z;
        }
    }

    // ---- staging assignments (fixed per thread) ----
    int ar0 = tid >> 2;              // rows 0..63
    int ar1 = 64 + ar0;              // rows 64..127
    int akq = (tid & 3) * 4;         // k-quad within chunk
    int tokA0 = s_tok[ar0], tokA1 = s_tok[ar1];
    const float* srcA0 = g_H + ((size_t)(tokA0 < 0 ? 0 : tokA0) << 9) + akq;
    const float* srcA1 = g_H + ((size_t)(tokA1 < 0 ? 0 : tokA1) << 9) + akq;
    int szA0 = (tokA0 < 0) ? 0 : 16;
    int szA1 = (tokA1 < 0) ? 0 : 16;
    int bk = tid >> 4;               // 0..15 (B k-row)
    int bn = (tid & 15) * 4;         // 0..60
    const float* __restrict__ Bg = g_Btf + ((size_t)e * HDIM * 256);

    uint32_t sbase = (uint32_t)__cvta_generic_to_shared(smg);
    const uint32_t BOFF = 3 * 128 * ASP * 4;   // byte offset of Bs

    auto stage = [&](int st, int cc) {
        int kk = cc * BK;
        uint32_t dA0 = sbase + ((st * 128 + ar0) * ASP + akq) * 4;
        uint32_t dA1 = sbase + ((st * 128 + ar1) * ASP + akq) * 4;
        CP_ASYNC_CG(dA0, srcA0 + kk, szA0);
        CP_ASYNC_CG(dA1, srcA1 + kk, szA1);
        uint32_t dB = sbase + BOFF + ((st * BK + bk) * BSP + bn) * 4;
        CP_ASYNC_CG(dB, Bg + (size_t)(kk + bk) * 256 + n0 + bn, 16);
    };

    int lane = tid & 31, wrp = tid >> 5;
    int wm = (wrp & 3) * 32;
    int wn = (wrp >> 2) * 32;
    int grp = lane >> 2, th4 = lane & 3;

    float c[2][4][4];
#pragma unroll
    for (int mt = 0; mt < 2; mt++)
#pragma unroll
        for (int nt = 0; nt < 4; nt++)
#pragma unroll
            for (int i = 0; i < 4; i++) c[mt][nt][i] = 0.f;

    stage(0, 0); CP_COMMIT();
    stage(1, 1); CP_COMMIT();

    int cur = 0;
    for (int cc = 0; cc < 32; cc++) {
        CP_WAIT1();
        __syncthreads();

        int ab = cur * 128;
        int bb = cur * BK;
#pragma unroll
        for (int k8 = 0; k8 < BK; k8 += 8) {
            int kb = k8 + th4;
            uint32_t a[2][4], b[4][2];
#pragma unroll
            for (int mt = 0; mt < 2; mt++) {
                int mb = ab + wm + mt * 16;
                a[mt][0] = As[mb + grp][kb];
                a[mt][1] = As[mb + 8 + grp][kb];
                a[mt][2] = As[mb + grp][kb + 4];
                a[mt][3] = As[mb + 8 + grp][kb + 4];
            }
#pragma unroll
            for (int nt = 0; nt < 4; nt++) {
                b[nt][0] = Bs[bb + kb][wn + nt * 8 + grp];
                b[nt][1] = Bs[bb + kb + 4][wn + nt * 8 + grp];
            }
#pragma unroll
            for (int mt = 0; mt < 2; mt++)
#pragma unroll
                for (int nt = 0; nt < 4; nt++)
                    mma_tf32(c[mt][nt], a[mt], b[nt]);
        }

        if (cc + 2 < 32) {
            int st = cur + 2; if (st >= 3) st -= 3;
            stage(st, cc + 2);
        }
        CP_COMMIT();
        if (++cur == 3) cur = 0;
    }

    // epilogue
    int seg = c_seg[e];
#pragma unroll
    for (int mt = 0; mt < 2; mt++) {
        int r0   = wm + mt * 16 + grp;
        int tok0 = s_tok[r0];
        int tok1 = s_tok[r0 + 8];
        if (tok0 >= 0) {
            float* o = p.out + (size_t)tok0 * OUTW + seg + n0 + wn + 2 * th4;
#pragma unroll
            for (int nt = 0; nt < 4; nt++)
                *(float2*)(o + nt * 8) = make_float2(c[mt][nt][0], c[mt][nt][1]);
        }
        if (tok1 >= 0) {
            float* o = p.out + (size_t)tok1 * OUTW + seg + n0 + wn + 2 * th4;
#pragma unroll
            for (int nt = 0; nt < 4; nt++)
                *(float2*)(o + nt * 8) = make_float2(c[mt][nt][2], c[mt][nt][3]);
        }
    }
}

// ---------------- host launcher ---------------------------------------------------
extern "C" void kernel_launch(void* const* d_in, const int* in_sizes, int n_in,
                              void* d_out, int out_size) {
    (void)in_sizes; (void)n_in; (void)out_size;
    // input order (setup_inputs dict order):
    // 0:A 1:X 2:Y 3:SP 4:P 5:PCH 6:PCL 7:Op 8:Val 9:fu_map
    // 10..24: (emb, W1, b1) x {alu, logic, move, flow, stack}
    // 25:alu_Wr 26:alu_Wf 27:logic_Wr 28:logic_Wf 29:move_Wo 30:flow_Wo 31:stack_Wo
    cudaFuncSetAttribute(precompute_T,
                         cudaFuncAttributeMaxDynamicSharedMemorySize, PT_SMEM);
    cudaFuncSetAttribute(gemm2_kernel,
                         cudaFuncAttributeMaxDynamicSharedMemorySize, G2_SMEM);

    PTP pt;
    HP  hp;
    for (int i = 0; i < 9; i++) hp.base[i] = (const int*)d_in[i];
    for (int e = 0; e < 5; e++) {
        pt.emb[e] = (const float*)d_in[10 + 3 * e];
        pt.W1[e]  = (const float*)d_in[11 + 3 * e];
        hp.b1[e]  = (const float*)d_in[12 + 3 * e];
    }
    FP fp;
    fp.Wf[0] = (const float*)d_in[26];
    fp.Wf[1] = (const float*)d_in[28];
    fp.out   = (float*)d_out;

    CP cp;
    cp.B[0] = (const float*)d_in[25];
    cp.B[1] = (const float*)d_in[27];
    cp.B[2] = (const float*)d_in[29];
    cp.B[3] = (const float*)d_in[30];
    cp.B[4] = (const float*)d_in[31];

    G2P p2;
    p2.out = (float*)d_out;

    const int* Op = (const int*)d_in[7];
    const int* fu = (const int*)d_in[9];

    int nblk = (NTOK + 5 * HDIM * 256) / 256;                 // compaction + cvtB
    compact_kernel<<<nblk, 256>>>(Op, fu, cp);                // launch 0
    precompute_T<<<dim3(4, 4, 30), 256, PT_SMEM>>>(pt);       // launch 1
    h_kernel<<<dim3(1024, 5), 256>>>(hp);                     // launch 2
    gemm2_kernel<<<dim3(4, 512, 5), 256, G2_SMEM>>>(p2);      // launch 3 (profiled)
    flag_kernel<<<dim3(2048, 2), 256>>>(fp);                  // launch 4
    reset_counts<<<1, 32>>>();                                // launch 5
}

// round 13
// speedup vs baseline: 1.7957x; 1.0650x over previous
#include <cuda_runtime.h>
#include <cstdint>
#include <cstddef>

// ============================================================================
// Swarm6502 masked 5-expert MoE. R13 = R12 with gemm2:
//  - zero-fill distributed across all n-blocks (was all in n0==0 -> imbalance)
//  - 4-stage cp.async pipeline (3 chunks in flight)
// Pipeline: compact(+cvtB) -> precompute_T -> h -> gemm2 -> flag -> reset
// ============================================================================

#define NTOK 65536
#define HDIM 512
#define OUTW 1296
#define BK   16
#define ASP  20    // As row stride: conflict-free a-frag LDS
#define BSP  72    // Bs row stride: conflict-free b-frag LDS
#define NSTG 4

__device__ int   g_counts[5];                        // zero-init at load
__device__ int   g_lists[5][NTOK];
__device__ float g_H[(size_t)NTOK * HDIM];           // tf32-rounded hidden
__device__ float g_T[(size_t)5 * 6 * 256 * HDIM];    // lookup tables
__device__ float g_Btf[5 * HDIM * 256];              // tf32-rounded B matrices

// index source codes: 0=A 1=X 2=Y 3=SP 4=P 5=PCH 6=PCL 7=Op 8=Val 9=carry(P&1)
__constant__ int c_code[5][6] = {
    {0, 8, 9, 7, -1, -1},   // alu
    {0, 8, 9, 7, -1, -1},   // logic
    {0, 1, 2, 8, 7, -1},    // move
    {5, 6, 4, 8, 3, 7},     // flow
    {0, 1, 3, 4, 8, 7}      // stack
};
__constant__ int c_k[5]    = {4, 4, 5, 6, 6};
__constant__ int c_nout[5] = {264, 264, 256, 256, 256};
__constant__ int c_seg[5]  = {0, 264, 528, 784, 1040};

struct PTP { const float* emb[5]; const float* W1[5]; };
struct HP  { const int* base[9]; const float* b1[5]; };
struct FP  { const float* Wf[2]; float* out; };
struct CP  { const float* B[5]; };
struct G2P { float* out; };

__device__ __forceinline__ float gelu_tanh(float x) {
    float x3 = x * x * x;
    float t  = tanhf(0.7978845608028654f * (x + 0.044715f * x3));
    return 0.5f * x * (1.0f + t);
}
__device__ __forceinline__ uint32_t f2tf32(float x) {
    uint32_t r;
    asm("cvt.rna.tf32.f32 %0, %1;" : "=r"(r) : "f"(x));
    return r;
}
__device__ __forceinline__ void mma_tf32(float* c, const uint32_t* a,
                                         const uint32_t* b) {
    asm volatile(
        "mma.sync.aligned.m16n8k8.row.col.f32.tf32.tf32.f32 "
        "{%0,%1,%2,%3}, {%4,%5,%6,%7}, {%8,%9}, {%0,%1,%2,%3};"
        : "+f"(c[0]), "+f"(c[1]), "+f"(c[2]), "+f"(c[3])
        : "r"(a[0]), "r"(a[1]), "r"(a[2]), "r"(a[3]), "r"(b[0]), "r"(b[1]));
}
#define CP_ASYNC_CG(dst, src, sz) \
    asm volatile("cp.async.cg.shared.global [%0], [%1], 16, %2;" \
                 :: "r"(dst), "l"(src), "r"(sz))
#define CP_COMMIT() asm volatile("cp.async.commit_group;")
#define CP_WAIT2()  asm volatile("cp.async.wait_group 2;")

// ---------------- compact + cvtB (one launch; counts zero on entry) -------------
__global__ void compact_kernel(const int* __restrict__ Op,
                               const int* __restrict__ fu_map, CP p) {
    long gid = (long)blockIdx.x * blockDim.x + threadIdx.x;
    if (gid < NTOK) {
        int e   = fu_map[Op[gid]];
        int pos = atomicAdd(&g_counts[e], 1);
        g_lists[e][pos] = (int)gid;
    } else {
        long i = gid - NTOK;                 // 0 .. 5*131072-1
        if (i < 5L * HDIM * 256) {
            int e = (int)(i >> 17);
            int r = (int)(i & (HDIM * 256 - 1));
            g_Btf[i] = __uint_as_float(f2tf32(__ldg(p.B[e] + r)));
        }
    }
}
__global__ void reset_counts() {
    if (threadIdx.x < 5) g_counts[threadIdx.x] = 0;
}

// ---------------- precompute T[e][j] = emb_ej @ W1_ej ---------------------------
#define PT_SMEM ((64 * 65 + 64 * 128) * 4)
__global__ void __launch_bounds__(256) precompute_T(PTP p) {
    int z = blockIdx.z, e = z / 6, j = z % 6;
    if (j >= c_k[e]) return;
    int v0 = blockIdx.x * 64;
    int n0 = blockIdx.y * 128;

    extern __shared__ float smp[];
    float (*Es)[65]  = (float(*)[65])smp;
    float (*Ws)[128] = (float(*)[128])(smp + 64 * 65);
    int tid = threadIdx.x;

    {
        int r = tid >> 2, c = (tid & 3) * 16;
        const float* src = p.emb[e] + ((size_t)j * 256 + v0 + r) * 64 + c;
#pragma unroll
        for (int q = 0; q < 16; q++) Es[r][c + q] = __ldg(src + q);
    }
    {
        int r = tid >> 2, c0 = (tid & 3) * 32;
        const float4* src =
            (const float4*)(p.W1[e] + ((size_t)(j * 64 + r)) * HDIM + n0 + c0);
        float4* dst = (float4*)&Ws[r][c0];
#pragma unroll
        for (int q = 0; q < 8; q++) dst[q] = __ldg(src + q);
    }
    __syncthreads();

    float acc[4][8];
#pragma unroll
    for (int i = 0; i < 4; i++)
#pragma unroll
        for (int jj = 0; jj < 8; jj++) acc[i][jj] = 0.f;

    int tm = (tid >> 4) * 4, tn = (tid & 15) * 8;
#pragma unroll
    for (int k = 0; k < 64; k++) {
        float a[4], b[8];
#pragma unroll
        for (int i = 0; i < 4; i++) a[i] = Es[tm + i][k];
        float4 b0 = *(const float4*)&Ws[k][tn];
        float4 b1 = *(const float4*)&Ws[k][tn + 4];
        b[0] = b0.x; b[1] = b0.y; b[2] = b0.z; b[3] = b0.w;
        b[4] = b1.x; b[5] = b1.y; b[6] = b1.z; b[7] = b1.w;
#pragma unroll
        for (int i = 0; i < 4; i++)
#pragma unroll
            for (int jj = 0; jj < 8; jj++)
                acc[i][jj] = fmaf(a[i], b[jj], acc[i][jj]);
    }

    float* T = g_T + ((size_t)(e * 6 + j) * 256) * HDIM;
#pragma unroll
    for (int i = 0; i < 4; i++) {
        float* d = T + (size_t)(v0 + tm + i) * HDIM + n0 + tn;
        *(float4*)d       = make_float4(acc[i][0], acc[i][1], acc[i][2], acc[i][3]);
        *(float4*)(d + 4) = make_float4(acc[i][4], acc[i][5], acc[i][6], acc[i][7]);
    }
}

// ---------------- h v2: smem-staged indices -> independent gathers ---------------
__global__ void __launch_bounds__(256) h_kernel(HP p) {
    int e  = blockIdx.y;
    int C  = g_counts[e];
    int m0 = blockIdx.x * 64;
    if (m0 >= C) return;

    __shared__ int s_tok[64];
    __shared__ int s_idx[6][64];

    int tid = threadIdx.x;
    int kc  = c_k[e];
    if (tid < 64) {
        int m = m0 + tid;
        s_tok[tid] = (m < C) ? g_lists[e][m] : -1;
    }
    __syncthreads();
    for (int u = tid; u < kc * 64; u += 256) {
        int j = u >> 6, m = u & 63;
        int tok = s_tok[m];
        int idx = 0;
        if (tok >= 0) {
            int code = c_code[e][j];
            idx = (code == 9) ? (__ldg(p.base[4] + tok) & 1)
                              : __ldg(p.base[code] + tok);
        }
        s_idx[j][m] = idx;
    }
    __syncthreads();

    int g = tid >> 7, t = tid & 127;
    float4 bias = __ldg((const float4*)p.b1[e] + t);
    const float* Tb = g_T + ((size_t)(e * 6) << 17);

    for (int lm = g * 32; lm < g * 32 + 32; lm += 2) {
        int tok0 = s_tok[lm], tok1 = s_tok[lm + 1];
        if (tok0 < 0) continue;
        float4 a0 = bias, a1 = bias;
        for (int j = 0; j < kc; j++) {
            float4 v0 = ((const float4*)(
                Tb + (((size_t)j * 256 + s_idx[j][lm]) << 9)))[t];
            a0.x += v0.x; a0.y += v0.y; a0.z += v0.z; a0.w += v0.w;
            if (tok1 >= 0) {
                float4 v1 = ((const float4*)(
                    Tb + (((size_t)j * 256 + s_idx[j][lm + 1]) << 9)))[t];
                a1.x += v1.x; a1.y += v1.y; a1.z += v1.z; a1.w += v1.w;
            }
        }
        float4 o0;
        o0.x = __uint_as_float(f2tf32(gelu_tanh(a0.x)));
        o0.y = __uint_as_float(f2tf32(gelu_tanh(a0.y)));
        o0.z = __uint_as_float(f2tf32(gelu_tanh(a0.z)));
        o0.w = __uint_as_float(f2tf32(gelu_tanh(a0.w)));
        ((float4*)(g_H + ((size_t)tok0 << 9)))[t] = o0;
        if (tok1 >= 0) {
            float4 o1;
            o1.x = __uint_as_float(f2tf32(gelu_tanh(a1.x)));
            o1.y = __uint_as_float(f2tf32(gelu_tanh(a1.y)));
            o1.z = __uint_as_float(f2tf32(gelu_tanh(a1.z)));
            o1.w = __uint_as_float(f2tf32(gelu_tanh(a1.w)));
            ((float4*)(g_H + ((size_t)tok1 << 9)))[t] = o1;
        }
    }
}

// ---------------- flag cols (alu/logic) ------------------------------------------
__global__ void __launch_bounds__(256) flag_kernel(FP p) {
    int e  = blockIdx.y;
    int C  = g_counts[e];
    int m0 = blockIdx.x * 32;
    if (m0 >= C) return;

    __shared__ float sWf[HDIM][8];
    int tid = threadIdx.x;
    const float4* Wf4 = (const float4*)p.Wf[e];
#pragma unroll
    for (int i = 0; i < 4; i++)
        ((float4*)sWf)[tid + i * 256] = __ldg(Wf4 + tid + i * 256);
    __syncthreads();

    int r = tid >> 3, f = tid & 7;
    int mi = m0 + r;
    if (mi >= C) return;
    int tok = g_lists[e][mi];
    const float4* h = (const float4*)(g_H + ((size_t)tok << 9));
    float dot = 0.f;
#pragma unroll 4
    for (int k4 = 0; k4 < 128; k4++) {
        float4 hv = __ldg(h + k4);
        dot += hv.x * sWf[k4 * 4 + 0][f];
        dot += hv.y * sWf[k4 * 4 + 1][f];
        dot += hv.z * sWf[k4 * 4 + 2][f];
        dot += hv.w * sWf[k4 * 4 + 3][f];
    }
    p.out[(size_t)tok * OUTW + c_seg[e] + 256 + f] = dot;
}

// ---------------- gemm2 v6: 4-stage cp.async, distributed zero-fill --------------
// (C x 512) @ (512 x 256). BM=128, BN=64, BK=16, 32 chunks, 4 stages, 8 warps.
// warp tile 32x32. grid (4, 512, 5): n0 inner -> A tile L2-shared by 4 blocks.
#define G2_SMEM (NSTG * (128 * ASP + BK * BSP) * 4)
__global__ void __launch_bounds__(256, 3) gemm2_kernel(G2P p) {
    int e  = blockIdx.z;
    int C  = g_counts[e];
    int m0 = blockIdx.y * 128;
    if (m0 >= C) return;
    int n0 = blockIdx.x * 64;

    extern __shared__ uint32_t smg[];
    uint32_t (*As)[ASP] = (uint32_t(*)[ASP])smg;                      // [NSTG*128][ASP]
    uint32_t (*Bs)[BSP] = (uint32_t(*)[BSP])(smg + NSTG * 128 * ASP); // [NSTG*BK][BSP]
    __shared__ int s_tok[128];

    int tid = threadIdx.x;
    if (tid < 128) {
        int m = m0 + tid;
        s_tok[tid] = (m < C) ? g_lists[e][m] : -1;
    }
    __syncthreads();

    // zero-fill complement, distributed across the 4 n-blocks of this m-tile
    {
        int s4 = c_seg[e] >> 2;
        int e4 = (c_seg[e] + c_nout[e]) >> 2;
        float4* out4 = (float4*)p.out;
        float4 z = make_float4(0.f, 0.f, 0.f, 0.f);
        for (int u = tid + (int)blockIdx.x * 256; u < 128 * (OUTW / 4);
             u += 1024) {
            int m = u / (OUTW / 4);
            int f = u - m * (OUTW / 4);
            if (f >= s4 && f < e4) continue;
            int tok = s_tok[m];
            if (tok < 0) continue;
            out4[(size_t)tok * (OUTW / 4) + f] = z;
        }
    }

    // ---- staging assignments (fixed per thread) ----
    int ar0 = tid >> 2;              // rows 0..63
    int ar1 = 64 + ar0;              // rows 64..127
    int akq = (tid & 3) * 4;         // k-quad within chunk
    int tokA0 = s_tok[ar0], tokA1 = s_tok[ar1];
    const float* srcA0 = g_H + ((size_t)(tokA0 < 0 ? 0 : tokA0) << 9) + akq;
    const float* srcA1 = g_H + ((size_t)(tokA1 < 0 ? 0 : tokA1) << 9) + akq;
    int szA0 = (tokA0 < 0) ? 0 : 16;
    int szA1 = (tokA1 < 0) ? 0 : 16;
    int bk = tid >> 4;               // 0..15 (B k-row)
    int bn = (tid & 15) * 4;         // 0..60
    const float* __restrict__ Bg = g_Btf + ((size_t)e * HDIM * 256);

    uint32_t sbase = (uint32_t)__cvta_generic_to_shared(smg);
    const uint32_t BOFF = NSTG * 128 * ASP * 4;   // byte offset of Bs

    auto stage = [&](int st, int cc) {
        int kk = cc * BK;
        uint32_t dA0 = sbase + ((st * 128 + ar0) * ASP + akq) * 4;
        uint32_t dA1 = sbase + ((st * 128 + ar1) * ASP + akq) * 4;
        CP_ASYNC_CG(dA0, srcA0 + kk, szA0);
        CP_ASYNC_CG(dA1, srcA1 + kk, szA1);
        uint32_t dB = sbase + BOFF + ((st * BK + bk) * BSP + bn) * 4;
        CP_ASYNC_CG(dB, Bg + (size_t)(kk + bk) * 256 + n0 + bn, 16);
    };

    int lane = tid & 31, wrp = tid >> 5;
    int wm = (wrp & 3) * 32;
    int wn = (wrp >> 2) * 32;
    int grp = lane >> 2, th4 = lane & 3;

    float c[2][4][4];
#pragma unroll
    for (int mt = 0; mt < 2; mt++)
#pragma unroll
        for (int nt = 0; nt < 4; nt++)
#pragma unroll
            for (int i = 0; i < 4; i++) c[mt][nt][i] = 0.f;

    stage(0, 0); CP_COMMIT();
    stage(1, 1); CP_COMMIT();
    stage(2, 2); CP_COMMIT();

    int cur = 0;
    for (int cc = 0; cc < 32; cc++) {
        CP_WAIT2();
        __syncthreads();

        int ab = cur * 128;
        int bb = cur * BK;
#pragma unroll
        for (int k8 = 0; k8 < BK; k8 += 8) {
            int kb = k8 + th4;
            uint32_t a[2][4], b[4][2];
#pragma unroll
            for (int mt = 0; mt < 2; mt++) {
                int mb = ab + wm + mt * 16;
                a[mt][0] = As[mb + grp][kb];
                a[mt][1] = As[mb + 8 + grp][kb];
                a[mt][2] = As[mb + grp][kb + 4];
                a[mt][3] = As[mb + 8 + grp][kb + 4];
            }
#pragma unroll
            for (int nt = 0; nt < 4; nt++) {
                b[nt][0] = Bs[bb + kb][wn + nt * 8 + grp];
                b[nt][1] = Bs[bb + kb + 4][wn + nt * 8 + grp];
            }
#pragma unroll
            for (int mt = 0; mt < 2; mt++)
#pragma unroll
                for (int nt = 0; nt < 4; nt++)
                    mma_tf32(c[mt][nt], a[mt], b[nt]);
        }

        // refill the buffer chunk cc-1 used (all warps past it via the barrier)
        if (cc + 3 < 32) {
            int st = cur + 3; if (st >= NSTG) st -= NSTG;
            stage(st, cc + 3);
        }
        CP_COMMIT();
        if (++cur == NSTG) cur = 0;
    }

    // epilogue
    int seg = c_seg[e];
#pragma unroll
    for (int mt = 0; mt < 2; mt++) {
        int r0   = wm + mt * 16 + grp;
        int tok0 = s_tok[r0];
        int tok1 = s_tok[r0 + 8];
        if (tok0 >= 0) {
            float* o = p.out + (size_t)tok0 * OUTW + seg + n0 + wn + 2 * th4;
#pragma unroll
            for (int nt = 0; nt < 4; nt++)
                *(float2*)(o + nt * 8) = make_float2(c[mt][nt][0], c[mt][nt][1]);
        }
        if (tok1 >= 0) {
            float* o = p.out + (size_t)tok1 * OUTW + seg + n0 + wn + 2 * th4;
#pragma unroll
            for (int nt = 0; nt < 4; nt++)
                *(float2*)(o + nt * 8) = make_float2(c[mt][nt][2], c[mt][nt][3]);
        }
    }
}

// ---------------- host launcher ---------------------------------------------------
extern "C" void kernel_launch(void* const* d_in, const int* in_sizes, int n_in,
                              void* d_out, int out_size) {
    (void)in_sizes; (void)n_in; (void)out_size;
    // input order (setup_inputs dict order):
    // 0:A 1:X 2:Y 3:SP 4:P 5:PCH 6:PCL 7:Op 8:Val 9:fu_map
    // 10..24: (emb, W1, b1) x {alu, logic, move, flow, stack}
    // 25:alu_Wr 26:alu_Wf 27:logic_Wr 28:logic_Wf 29:move_Wo 30:flow_Wo 31:stack_Wo
    cudaFuncSetAttribute(precompute_T,
                         cudaFuncAttributeMaxDynamicSharedMemorySize, PT_SMEM);
    cudaFuncSetAttribute(gemm2_kernel,
                         cudaFuncAttributeMaxDynamicSharedMemorySize, G2_SMEM);

    PTP pt;
    HP  hp;
    for (int i = 0; i < 9; i++) hp.base[i] = (const int*)d_in[i];
    for (int e = 0; e < 5; e++) {
        pt.emb[e] = (const float*)d_in[10 + 3 * e];
        pt.W1[e]  = (const float*)d_in[11 + 3 * e];
        hp.b1[e]  = (const float*)d_in[12 + 3 * e];
    }
    FP fp;
    fp.Wf[0] = (const float*)d_in[26];
    fp.Wf[1] = (const float*)d_in[28];
    fp.out   = (float*)d_out;

    CP cp;
    cp.B[0] = (const float*)d_in[25];
    cp.B[1] = (const float*)d_in[27];
    cp.B[2] = (const float*)d_in[29];
    cp.B[3] = (const float*)d_in[30];
    cp.B[4] = (const float*)d_in[31];

    G2P p2;
    p2.out = (float*)d_out;

    const int* Op = (const int*)d_in[7];
    const int* fu = (const int*)d_in[9];

    int nblk = (NTOK + 5 * HDIM * 256) / 256;                 // compaction + cvtB
    compact_kernel<<<nblk, 256>>>(Op, fu, cp);                // launch 0
    precompute_T<<<dim3(4, 4, 30), 256, PT_SMEM>>>(pt);       // launch 1
    h_kernel<<<dim3(1024, 5), 256>>>(hp);                     // launch 2
    gemm2_kernel<<<dim3(4, 512, 5), 256, G2_SMEM>>>(p2);      // launch 3 (profiled)
    flag_kernel<<<dim3(2048, 2), 256>>>(fp);                  // launch 4
    reset_counts<<<1, 32>>>();                                // launch 5
}